// round 6
// baseline (speedup 1.0000x reference)
#include <cuda_runtime.h>
#include <cuda_bf16.h>
#include <math.h>

#define B_DIM 4
#define T_DIM 2048
#define C_DIM 1024
#define H_NUM 16
#define D_DIM 64
#define M_ROWS (B_DIM * T_DIM)   // 8192

// Scratch (device globals — no allocation allowed)
__device__ float g_q[(size_t)M_ROWS * C_DIM];   // [B,H,T,D]
__device__ float g_k[(size_t)M_ROWS * C_DIM];   // [B,H,T,D]
__device__ float g_v[(size_t)M_ROWS * C_DIM];   // [B,H,T,D]
__device__ float g_y[(size_t)M_ROWS * C_DIM];   // [B,T,C]

// ---------------------------------------------------------------------------
// NT SGEMM: C[m,n] = sum_k A[m,k] * W[n,k] + bias[n]
// 128x128 tile, BK=8, 256 threads, 8x8 per thread.
// REMAP=0: out[m*C + n]   (row-major [M, C])
// REMAP=1: out[((b*H + h)*T + t)*D + d]  with b=m/T, t=m%T, h=n/D, d=n%D
// ---------------------------------------------------------------------------
template <int REMAP>
__device__ __forceinline__ void gemm_body(const float* __restrict__ A,
                                          const float* __restrict__ W,
                                          const float* __restrict__ bias,
                                          float* __restrict__ out)
{
    __shared__ float As[8][128];
    __shared__ float Ws[8][128];

    const int tid = threadIdx.x;
    const int tx = tid & 15;
    const int ty = tid >> 4;
    const int bm = blockIdx.y * 128;
    const int bn = blockIdx.x * 128;

    const int lrow = tid >> 1;          // 0..127
    const int lk4  = (tid & 1) << 2;    // 0 or 4

    float acc[8][8];
#pragma unroll
    for (int i = 0; i < 8; i++)
#pragma unroll
        for (int j = 0; j < 8; j++) acc[i][j] = 0.0f;

    for (int k0 = 0; k0 < C_DIM; k0 += 8) {
        float4 av = *(const float4*)&A[(size_t)(bm + lrow) * C_DIM + k0 + lk4];
        float4 wv = *(const float4*)&W[(size_t)(bn + lrow) * C_DIM + k0 + lk4];
        __syncthreads();   // guard previous iteration's smem reads
        As[lk4 + 0][lrow] = av.x; As[lk4 + 1][lrow] = av.y;
        As[lk4 + 2][lrow] = av.z; As[lk4 + 3][lrow] = av.w;
        Ws[lk4 + 0][lrow] = wv.x; Ws[lk4 + 1][lrow] = wv.y;
        Ws[lk4 + 2][lrow] = wv.z; Ws[lk4 + 3][lrow] = wv.w;
        __syncthreads();
#pragma unroll
        for (int kk = 0; kk < 8; kk++) {
            float ar[8], wr[8];
            *(float4*)&ar[0] = *(const float4*)&As[kk][ty * 8];
            *(float4*)&ar[4] = *(const float4*)&As[kk][ty * 8 + 4];
            *(float4*)&wr[0] = *(const float4*)&Ws[kk][tx * 8];
            *(float4*)&wr[4] = *(const float4*)&Ws[kk][tx * 8 + 4];
#pragma unroll
            for (int i = 0; i < 8; i++)
#pragma unroll
                for (int j = 0; j < 8; j++)
                    acc[i][j] = fmaf(ar[i], wr[j], acc[i][j]);
        }
    }

    float bj[8];
#pragma unroll
    for (int j = 0; j < 8; j++) bj[j] = bias[bn + tx * 8 + j];

#pragma unroll
    for (int i = 0; i < 8; i++) {
        const int m = bm + ty * 8 + i;
#pragma unroll
        for (int j = 0; j < 8; j++) {
            const int n = bn + tx * 8 + j;
            const float v = acc[i][j] + bj[j];
            if (REMAP == 0) {
                out[(size_t)m * C_DIM + n] = v;
            } else {
                const int b = m >> 11;          // m / T
                const int t = m & (T_DIM - 1);
                const int h = n >> 6;           // n / D
                const int d = n & (D_DIM - 1);
                out[(((size_t)(b * H_NUM + h)) * T_DIM + t) * D_DIM + d] = v;
            }
        }
    }
}

__global__ void __launch_bounds__(256)
qkv_gemm_kernel(const float* __restrict__ X,
                const float* __restrict__ Wq, const float* __restrict__ bq,
                const float* __restrict__ Wk, const float* __restrict__ bk,
                const float* __restrict__ Wv, const float* __restrict__ bv)
{
    const float* W; const float* bias; float* out;
    if (blockIdx.z == 0)      { W = Wq; bias = bq; out = g_q; }
    else if (blockIdx.z == 1) { W = Wk; bias = bk; out = g_k; }
    else                      { W = Wv; bias = bv; out = g_v; }
    gemm_body<1>(X, W, bias, out);
}

__global__ void __launch_bounds__(256)
out_gemm_kernel(const float* __restrict__ Wo, const float* __restrict__ bo,
                float* __restrict__ out)
{
    gemm_body<0>(g_y, Wo, bo, out);
}

// ---------------------------------------------------------------------------
// Flash attention: one block per (q-tile of 64 rows, b*h).
// 256 threads (16x16). Each thread owns a 4x4 patch of the 64x64 score tile
// and a 4(rows) x 4(d-cols) patch of the output accumulator.
// Static smem = exactly 48 KB (no dynamic smem, no cudaFuncSetAttribute):
//   Qs [d][r]  (pre-scaled)                16 KB
//   KPs: K tile [d][c], reused as P [r][c] 16 KB
//   Vs [c][d]                              16 KB
// ---------------------------------------------------------------------------
__global__ void __launch_bounds__(256)
flash_attn_kernel(float scale)
{
    __shared__ float Qs [64 * 64];
    __shared__ float KPs[64 * 64];
    __shared__ float Vs [64 * 64];

    const int tid = threadIdx.x;
    const int tx = tid & 15;
    const int ty = tid >> 4;
    const int bh = blockIdx.y;                 // 0..63
    const int q0 = blockIdx.x * 64;

    const float* Qg = g_q + (size_t)bh * T_DIM * D_DIM;
    const float* Kg = g_k + (size_t)bh * T_DIM * D_DIM;
    const float* Vg = g_v + (size_t)bh * T_DIM * D_DIM;

    // Load Q tile transposed (d-major), pre-scaled by 1/sqrt(D)
#pragma unroll
    for (int e = tid; e < 64 * 16; e += 256) {
        const int r  = e >> 4;
        const int d4 = (e & 15) << 2;
        float4 qv = *(const float4*)&Qg[(size_t)(q0 + r) * D_DIM + d4];
        Qs[(d4 + 0) * 64 + r] = qv.x * scale;
        Qs[(d4 + 1) * 64 + r] = qv.y * scale;
        Qs[(d4 + 2) * 64 + r] = qv.z * scale;
        Qs[(d4 + 3) * 64 + r] = qv.w * scale;
    }

    float mrow[4], lrow[4], O[4][4];
#pragma unroll
    for (int i = 0; i < 4; i++) {
        mrow[i] = -1e30f; lrow[i] = 0.0f;
#pragma unroll
        for (int j = 0; j < 4; j++) O[i][j] = 0.0f;
    }

    for (int kt = 0; kt < T_DIM / 64; kt++) {
        const int k0 = kt * 64;
        __syncthreads();   // guard prev iteration's KPs/Vs reads (and Q writes, iter 0)
        // Load K tile transposed (d-major) and V tile (c-major)
#pragma unroll
        for (int e = tid; e < 64 * 16; e += 256) {
            const int c  = e >> 4;
            const int d4 = (e & 15) << 2;
            float4 kv = *(const float4*)&Kg[(size_t)(k0 + c) * D_DIM + d4];
            KPs[(d4 + 0) * 64 + c] = kv.x;
            KPs[(d4 + 1) * 64 + c] = kv.y;
            KPs[(d4 + 2) * 64 + c] = kv.z;
            KPs[(d4 + 3) * 64 + c] = kv.w;
            float4 vv = *(const float4*)&Vg[(size_t)(k0 + c) * D_DIM + d4];
            *(float4*)&Vs[c * 64 + d4] = vv;
        }
        __syncthreads();

        // S = Q * K^T  (rows ty*4.., cols tx*4..)
        float S[4][4];
#pragma unroll
        for (int i = 0; i < 4; i++)
#pragma unroll
            for (int j = 0; j < 4; j++) S[i][j] = 0.0f;

#pragma unroll 8
        for (int d = 0; d < 64; d++) {
            float4 qv = *(const float4*)&Qs[d * 64 + ty * 4];
            float4 kv = *(const float4*)&KPs[d * 64 + tx * 4];
            const float qa[4] = {qv.x, qv.y, qv.z, qv.w};
            const float ka[4] = {kv.x, kv.y, kv.z, kv.w};
#pragma unroll
            for (int i = 0; i < 4; i++)
#pragma unroll
                for (int j = 0; j < 4; j++)
                    S[i][j] = fmaf(qa[i], ka[j], S[i][j]);
        }

        // Online softmax update (row groups span the 16 tx-lanes sharing ty)
#pragma unroll
        for (int i = 0; i < 4; i++) {
            float mx = fmaxf(fmaxf(S[i][0], S[i][1]), fmaxf(S[i][2], S[i][3]));
#pragma unroll
            for (int off = 8; off >= 1; off >>= 1)
                mx = fmaxf(mx, __shfl_xor_sync(0xffffffffu, mx, off));
            const float mnew = fmaxf(mrow[i], mx);
            const float corr = __expf(mrow[i] - mnew);
            mrow[i] = mnew;
            float rs = 0.0f;
#pragma unroll
            for (int j = 0; j < 4; j++) {
                S[i][j] = __expf(S[i][j] - mnew);
                rs += S[i][j];
            }
#pragma unroll
            for (int off = 8; off >= 1; off >>= 1)
                rs += __shfl_xor_sync(0xffffffffu, rs, off);
            lrow[i] = lrow[i] * corr + rs;
#pragma unroll
            for (int j = 0; j < 4; j++) O[i][j] *= corr;
        }

        // K tile is dead now; reuse KPs as P, ROW-major: P[r*64 + c].
        __syncthreads();   // all threads done reading K from KPs
#pragma unroll
        for (int i = 0; i < 4; i++) {
            float4 pv;
            pv.x = S[i][0]; pv.y = S[i][1]; pv.z = S[i][2]; pv.w = S[i][3];
            *(float4*)&KPs[(ty * 4 + i) * 64 + tx * 4] = pv;
        }
        __syncthreads();

        // O += P * V   (rows ty*4.., d-cols tx*4..)
        // P read is a per-row scalar broadcast (all tx lanes same address).
#pragma unroll 8
        for (int c = 0; c < 64; c++) {
            float pa[4];
#pragma unroll
            for (int i = 0; i < 4; i++)
                pa[i] = KPs[(ty * 4 + i) * 64 + c];
            float4 vv = *(const float4*)&Vs[c * 64 + tx * 4];
            const float va[4] = {vv.x, vv.y, vv.z, vv.w};
#pragma unroll
            for (int i = 0; i < 4; i++)
#pragma unroll
                for (int j = 0; j < 4; j++)
                    O[i][j] = fmaf(pa[i], va[j], O[i][j]);
        }
    }

    // Epilogue: normalize and write to g_y in [B, T, C] layout
    const int b = bh >> 4;
    const int h = bh & 15;
#pragma unroll
    for (int i = 0; i < 4; i++) {
        const float inv = 1.0f / lrow[i];
        const int t = q0 + ty * 4 + i;
        float4 ov;
        ov.x = O[i][0] * inv; ov.y = O[i][1] * inv;
        ov.z = O[i][2] * inv; ov.w = O[i][3] * inv;
        *(float4*)&g_y[((size_t)b * T_DIM + t) * C_DIM + h * D_DIM + tx * 4] = ov;
    }
}

// ---------------------------------------------------------------------------
extern "C" void kernel_launch(void* const* d_in, const int* in_sizes, int n_in,
                              void* d_out, int out_size)
{
    const float* x  = (const float*)d_in[0];
    const float* Wq = (const float*)d_in[1];
    const float* bq = (const float*)d_in[2];
    const float* Wk = (const float*)d_in[3];
    const float* bk = (const float*)d_in[4];
    const float* Wv = (const float*)d_in[5];
    const float* bv = (const float*)d_in[6];
    const float* Wo = (const float*)d_in[7];
    const float* bo = (const float*)d_in[8];
    float* out = (float*)d_out;

    // 1) QKV projections -> g_q/g_k/g_v in [B,H,T,D]
    {
        dim3 grid(C_DIM / 128, M_ROWS / 128, 3);
        qkv_gemm_kernel<<<grid, 256>>>(x, Wq, bq, Wk, bk, Wv, bv);
    }

    // 2) Flash attention -> g_y in [B,T,C]
    {
        dim3 grid(T_DIM / 64, B_DIM * H_NUM);
        const float scale = 1.0f / sqrtf((float)D_DIM);
        flash_attn_kernel<<<grid, 256>>>(scale);
    }

    // 3) Output projection -> d_out
    {
        dim3 grid(C_DIM / 128, M_ROWS / 128);
        out_gemm_kernel<<<grid, 256>>>(Wo, bo, out);
    }
}

// round 8
// speedup vs baseline: 1.3443x; 1.3443x over previous
#include <cuda_runtime.h>
#include <cuda_bf16.h>
#include <cstdint>
#include <math.h>

#define B_DIM 4
#define T_DIM 2048
#define C_DIM 1024
#define H_NUM 16
#define D_DIM 64
#define M_ROWS (B_DIM * T_DIM)   // 8192

// ---------------------------------------------------------------------------
// Scratch (device globals — no allocation allowed)
// ---------------------------------------------------------------------------
__device__ float g_q[(size_t)M_ROWS * C_DIM];   // [B,H,T,D] fp32
__device__ float g_k[(size_t)M_ROWS * C_DIM];
__device__ float g_v[(size_t)M_ROWS * C_DIM];
__device__ float g_y[(size_t)M_ROWS * C_DIM];   // [B,T,C] fp32

__device__ __nv_bfloat16 g_xhi[(size_t)M_ROWS * C_DIM];
__device__ __nv_bfloat16 g_xlo[(size_t)M_ROWS * C_DIM];
__device__ __nv_bfloat16 g_whi[(size_t)3 * C_DIM * C_DIM];  // Wq,Wk,Wv
__device__ __nv_bfloat16 g_wlo[(size_t)3 * C_DIM * C_DIM];
__device__ __nv_bfloat16 g_wohi[(size_t)C_DIM * C_DIM];
__device__ __nv_bfloat16 g_wolo[(size_t)C_DIM * C_DIM];
__device__ __nv_bfloat16 g_yhi[(size_t)M_ROWS * C_DIM];
__device__ __nv_bfloat16 g_ylo[(size_t)M_ROWS * C_DIM];

// ---------------------------------------------------------------------------
// mma.sync helpers (legacy HMMA path — works on plain sm_103 target)
// ---------------------------------------------------------------------------
__device__ __forceinline__ uint32_t smem_u32(const void* p) {
    uint32_t a;
    asm("{ .reg .u64 t; cvta.to.shared.u64 t, %1; cvt.u32.u64 %0, t; }"
        : "=r"(a) : "l"(p));
    return a;
}

__device__ __forceinline__ void ldmatrix_x4(uint32_t& r0, uint32_t& r1,
                                            uint32_t& r2, uint32_t& r3,
                                            uint32_t addr)
{
    asm volatile("ldmatrix.sync.aligned.m8n8.x4.shared.b16 {%0,%1,%2,%3}, [%4];"
                 : "=r"(r0), "=r"(r1), "=r"(r2), "=r"(r3) : "r"(addr));
}

__device__ __forceinline__ void mma_16816(float* c, const uint32_t* a,
                                          const uint32_t* b)
{
    asm volatile(
        "mma.sync.aligned.m16n8k16.row.col.f32.bf16.bf16.f32 "
        "{%0,%1,%2,%3}, {%4,%5,%6,%7}, {%8,%9}, {%0,%1,%2,%3};"
        : "+f"(c[0]), "+f"(c[1]), "+f"(c[2]), "+f"(c[3])
        : "r"(a[0]), "r"(a[1]), "r"(a[2]), "r"(a[3]), "r"(b[0]), "r"(b[1]));
}

// ---------------------------------------------------------------------------
// Split fp32 -> bf16 hi/lo pair (bf16x3 error compensation inputs)
// sel: 0=x  1..3=W(q,k,v)  4=Wo  5=g_y
// ---------------------------------------------------------------------------
__global__ void __launch_bounds__(256)
split_sel_kernel(const float* __restrict__ src_in, int sel, int n4)
{
    int i = blockIdx.x * blockDim.x + threadIdx.x;
    if (i >= n4) return;

    const float* src = src_in;
    __nv_bfloat16* hi;
    __nv_bfloat16* lo;
    if (sel == 0)      { hi = g_xhi;  lo = g_xlo; }
    else if (sel <= 3) { size_t o = (size_t)(sel - 1) << 20; hi = g_whi + o; lo = g_wlo + o; }
    else if (sel == 4) { hi = g_wohi; lo = g_wolo; }
    else               { hi = g_yhi;  lo = g_ylo; src = g_y; }

    float4 v = *(const float4*)(src + (size_t)i * 4);
    float f[4] = {v.x, v.y, v.z, v.w};
    __nv_bfloat16 h[4], l[4];
#pragma unroll
    for (int j = 0; j < 4; j++) {
        h[j] = __float2bfloat16(f[j]);
        l[j] = __float2bfloat16(f[j] - __bfloat162float(h[j]));
    }
    __nv_bfloat162 hv0 = {h[0], h[1]}, hv1 = {h[2], h[3]};
    __nv_bfloat162 lv0 = {l[0], l[1]}, lv1 = {l[2], l[3]};
    *(__nv_bfloat162*)(hi + (size_t)i * 4)     = hv0;
    *(__nv_bfloat162*)(hi + (size_t)i * 4 + 2) = hv1;
    *(__nv_bfloat162*)(lo + (size_t)i * 4)     = lv0;
    *(__nv_bfloat162*)(lo + (size_t)i * 4 + 2) = lv1;
}

// ---------------------------------------------------------------------------
// mma.sync bf16x3 NT GEMM: out[m,n] = sum_k A[m,k]*B[n,k] + bias[n]
// CTA tile 128x128, 256 threads = 8 warps, warp tile 32(M) x 64(N).
// K chunks of 32 (2 k-steps of 16). Smem rows padded to 40 bf16 for
// conflict-free ldmatrix. hi/lo split: acc += Ahi*Bhi + Ahi*Blo + Alo*Bhi.
// REMAP=0: out[m*C+n].  REMAP=1: out[((b*H+h)*T+t)*D+d].
// ---------------------------------------------------------------------------
#define KC 32
#define LDS 40   // padded row length (bf16 elems)

template <int REMAP>
__device__ __forceinline__ void mma_gemm_body(
    const __nv_bfloat16* __restrict__ Ahi, const __nv_bfloat16* __restrict__ Alo,
    const __nv_bfloat16* __restrict__ Bhi, const __nv_bfloat16* __restrict__ Blo,
    const float* __restrict__ bias, float* __restrict__ out)
{
    __shared__ __nv_bfloat16 sAhi[128][LDS];
    __shared__ __nv_bfloat16 sAlo[128][LDS];
    __shared__ __nv_bfloat16 sBhi[128][LDS];
    __shared__ __nv_bfloat16 sBlo[128][LDS];

    const int tid  = threadIdx.x;
    const int lane = tid & 31;
    const int wid  = tid >> 5;
    const int wm   = wid & 3;    // M warp group: 32 rows
    const int wn   = wid >> 2;   // N warp group: 64 cols
    const int bm = blockIdx.y * 128;
    const int bn = blockIdx.x * 128;

    float acc[2][8][4];
#pragma unroll
    for (int i = 0; i < 2; i++)
#pragma unroll
        for (int j = 0; j < 8; j++)
#pragma unroll
            for (int c = 0; c < 4; c++) acc[i][j][c] = 0.0f;

    // Global load mapping: thread -> (row, 16-col half)
    const int lrow = tid >> 1;
    const int lcol = (tid & 1) << 4;   // 0 or 16
    const __nv_bfloat16* gAhi = Ahi + (size_t)(bm + lrow) * C_DIM + lcol;
    const __nv_bfloat16* gAlo = Alo + (size_t)(bm + lrow) * C_DIM + lcol;
    const __nv_bfloat16* gBhi = Bhi + (size_t)(bn + lrow) * C_DIM + lcol;
    const __nv_bfloat16* gBlo = Blo + (size_t)(bn + lrow) * C_DIM + lcol;

    // ldmatrix lane addressing (matrix idx = lane>>3, r = lane&7)
    const int lr = lane & 7;
    const int lm = lane >> 3;          // 0..3
    // A: row off = (lm&1)*8, col off = (lm>>1)*8
    const int a_row = wm * 32 + (lm & 1) * 8 + lr;
    const int a_col = (lm >> 1) * 8;
    // B: row off = (lm>>1)*8, col off = (lm&1)*8
    const int b_row = wn * 64 + (lm >> 1) * 8 + lr;
    const int b_col = (lm & 1) * 8;

    const uint32_t uAhi = smem_u32(&sAhi[0][0]);
    const uint32_t uAlo = smem_u32(&sAlo[0][0]);
    const uint32_t uBhi = smem_u32(&sBhi[0][0]);
    const uint32_t uBlo = smem_u32(&sBlo[0][0]);

    for (int kc = 0; kc < C_DIM / KC; kc++) {
        const int k0 = kc * KC;
        __syncthreads();   // guard previous iteration's smem reads
        *(uint4*)&sAhi[lrow][lcol]     = *(const uint4*)(gAhi + k0);
        *(uint4*)&sAhi[lrow][lcol + 8] = *(const uint4*)(gAhi + k0 + 8);
        *(uint4*)&sAlo[lrow][lcol]     = *(const uint4*)(gAlo + k0);
        *(uint4*)&sAlo[lrow][lcol + 8] = *(const uint4*)(gAlo + k0 + 8);
        *(uint4*)&sBhi[lrow][lcol]     = *(const uint4*)(gBhi + k0);
        *(uint4*)&sBhi[lrow][lcol + 8] = *(const uint4*)(gBhi + k0 + 8);
        *(uint4*)&sBlo[lrow][lcol]     = *(const uint4*)(gBlo + k0);
        *(uint4*)&sBlo[lrow][lcol + 8] = *(const uint4*)(gBlo + k0 + 8);
        __syncthreads();

#pragma unroll
        for (int ks = 0; ks < KC / 16; ks++) {
            const int ko = ks * 16;

            uint32_t afh[2][4], afl[2][4];
#pragma unroll
            for (int mi = 0; mi < 2; mi++) {
                const uint32_t off =
                    (uint32_t)((a_row + mi * 16) * LDS + ko + a_col) * 2u;
                ldmatrix_x4(afh[mi][0], afh[mi][1], afh[mi][2], afh[mi][3], uAhi + off);
                ldmatrix_x4(afl[mi][0], afl[mi][1], afl[mi][2], afl[mi][3], uAlo + off);
            }

            uint32_t bfh[8][2], bfl[8][2];
#pragma unroll
            for (int ni = 0; ni < 4; ni++) {
                const uint32_t off =
                    (uint32_t)((b_row + ni * 16) * LDS + ko + b_col) * 2u;
                uint32_t r0, r1, r2, r3;
                ldmatrix_x4(r0, r1, r2, r3, uBhi + off);
                bfh[ni * 2][0] = r0; bfh[ni * 2][1] = r1;
                bfh[ni * 2 + 1][0] = r2; bfh[ni * 2 + 1][1] = r3;
                ldmatrix_x4(r0, r1, r2, r3, uBlo + off);
                bfl[ni * 2][0] = r0; bfl[ni * 2][1] = r1;
                bfl[ni * 2 + 1][0] = r2; bfl[ni * 2 + 1][1] = r3;
            }

#pragma unroll
            for (int mi = 0; mi < 2; mi++)
#pragma unroll
                for (int nj = 0; nj < 8; nj++) {
                    mma_16816(acc[mi][nj], afh[mi], bfh[nj]);
                    mma_16816(acc[mi][nj], afh[mi], bfl[nj]);
                    mma_16816(acc[mi][nj], afl[mi], bfh[nj]);
                }
        }
    }

    // Epilogue: c0,c1 -> (row, col..col+1); c2,c3 -> (row+8, col..col+1)
#pragma unroll
    for (int mi = 0; mi < 2; mi++) {
#pragma unroll
        for (int nj = 0; nj < 8; nj++) {
#pragma unroll
            for (int cp = 0; cp < 2; cp++) {
                const int m = bm + wm * 32 + mi * 16 + (lane >> 2) + cp * 8;
                const int n = bn + wn * 64 + nj * 8 + (lane & 3) * 2;
                float2 v;
                v.x = acc[mi][nj][cp * 2 + 0] + bias[n];
                v.y = acc[mi][nj][cp * 2 + 1] + bias[n + 1];
                if (REMAP == 0) {
                    *(float2*)&out[(size_t)m * C_DIM + n] = v;
                } else {
                    const int b = m >> 11;
                    const int t = m & (T_DIM - 1);
                    const int h = n >> 6;
                    const int d = n & (D_DIM - 1);
                    *(float2*)&out[(((size_t)(b * H_NUM + h)) * T_DIM + t) * D_DIM + d] = v;
                }
            }
        }
    }
}

__global__ void __launch_bounds__(256, 1)
qkv_mma_kernel(const float* __restrict__ bq, const float* __restrict__ bk,
               const float* __restrict__ bv)
{
    const size_t z = blockIdx.z;
    const __nv_bfloat16* Bh = g_whi + (z << 20);
    const __nv_bfloat16* Bl = g_wlo + (z << 20);
    const float* bias;
    float* out;
    if (z == 0)      { bias = bq; out = g_q; }
    else if (z == 1) { bias = bk; out = g_k; }
    else             { bias = bv; out = g_v; }
    mma_gemm_body<1>(g_xhi, g_xlo, Bh, Bl, bias, out);
}

__global__ void __launch_bounds__(256, 1)
out_mma_kernel(const float* __restrict__ bo, float* __restrict__ out)
{
    mma_gemm_body<0>(g_yhi, g_ylo, g_wohi, g_wolo, bo, out);
}

// ---------------------------------------------------------------------------
// Flash attention (fp32 FFMA — unchanged passing version).
// One block per (64-row q-tile, b*h). 256 threads (16x16).
// Static smem 48 KB: Qs[d][r] (pre-scaled), KPs (K tile [d][c] reused as
// P [r][c]), Vs[c][d].
// ---------------------------------------------------------------------------
__global__ void __launch_bounds__(256)
flash_attn_kernel(float scale)
{
    __shared__ float Qs [64 * 64];
    __shared__ float KPs[64 * 64];
    __shared__ float Vs [64 * 64];

    const int tid = threadIdx.x;
    const int tx = tid & 15;
    const int ty = tid >> 4;
    const int bh = blockIdx.y;
    const int q0 = blockIdx.x * 64;

    const float* Qg = g_q + (size_t)bh * T_DIM * D_DIM;
    const float* Kg = g_k + (size_t)bh * T_DIM * D_DIM;
    const float* Vg = g_v + (size_t)bh * T_DIM * D_DIM;

#pragma unroll
    for (int e = tid; e < 64 * 16; e += 256) {
        const int r  = e >> 4;
        const int d4 = (e & 15) << 2;
        float4 qv = *(const float4*)&Qg[(size_t)(q0 + r) * D_DIM + d4];
        Qs[(d4 + 0) * 64 + r] = qv.x * scale;
        Qs[(d4 + 1) * 64 + r] = qv.y * scale;
        Qs[(d4 + 2) * 64 + r] = qv.z * scale;
        Qs[(d4 + 3) * 64 + r] = qv.w * scale;
    }

    float mrow[4], lrow[4], O[4][4];
#pragma unroll
    for (int i = 0; i < 4; i++) {
        mrow[i] = -1e30f; lrow[i] = 0.0f;
#pragma unroll
        for (int j = 0; j < 4; j++) O[i][j] = 0.0f;
    }

    for (int kt = 0; kt < T_DIM / 64; kt++) {
        const int k0 = kt * 64;
        __syncthreads();
#pragma unroll
        for (int e = tid; e < 64 * 16; e += 256) {
            const int c  = e >> 4;
            const int d4 = (e & 15) << 2;
            float4 kv = *(const float4*)&Kg[(size_t)(k0 + c) * D_DIM + d4];
            KPs[(d4 + 0) * 64 + c] = kv.x;
            KPs[(d4 + 1) * 64 + c] = kv.y;
            KPs[(d4 + 2) * 64 + c] = kv.z;
            KPs[(d4 + 3) * 64 + c] = kv.w;
            float4 vv = *(const float4*)&Vg[(size_t)(k0 + c) * D_DIM + d4];
            *(float4*)&Vs[c * 64 + d4] = vv;
        }
        __syncthreads();

        float S[4][4];
#pragma unroll
        for (int i = 0; i < 4; i++)
#pragma unroll
            for (int j = 0; j < 4; j++) S[i][j] = 0.0f;

#pragma unroll 8
        for (int d = 0; d < 64; d++) {
            float4 qv = *(const float4*)&Qs[d * 64 + ty * 4];
            float4 kv = *(const float4*)&KPs[d * 64 + tx * 4];
            const float qa[4] = {qv.x, qv.y, qv.z, qv.w};
            const float ka[4] = {kv.x, kv.y, kv.z, kv.w};
#pragma unroll
            for (int i = 0; i < 4; i++)
#pragma unroll
                for (int j = 0; j < 4; j++)
                    S[i][j] = fmaf(qa[i], ka[j], S[i][j]);
        }

#pragma unroll
        for (int i = 0; i < 4; i++) {
            float mx = fmaxf(fmaxf(S[i][0], S[i][1]), fmaxf(S[i][2], S[i][3]));
#pragma unroll
            for (int off = 8; off >= 1; off >>= 1)
                mx = fmaxf(mx, __shfl_xor_sync(0xffffffffu, mx, off));
            const float mnew = fmaxf(mrow[i], mx);
            const float corr = __expf(mrow[i] - mnew);
            mrow[i] = mnew;
            float rs = 0.0f;
#pragma unroll
            for (int j = 0; j < 4; j++) {
                S[i][j] = __expf(S[i][j] - mnew);
                rs += S[i][j];
            }
#pragma unroll
            for (int off = 8; off >= 1; off >>= 1)
                rs += __shfl_xor_sync(0xffffffffu, rs, off);
            lrow[i] = lrow[i] * corr + rs;
#pragma unroll
            for (int j = 0; j < 4; j++) O[i][j] *= corr;
        }

        __syncthreads();
#pragma unroll
        for (int i = 0; i < 4; i++) {
            float4 pv;
            pv.x = S[i][0]; pv.y = S[i][1]; pv.z = S[i][2]; pv.w = S[i][3];
            *(float4*)&KPs[(ty * 4 + i) * 64 + tx * 4] = pv;
        }
        __syncthreads();

#pragma unroll 8
        for (int c = 0; c < 64; c++) {
            float pa[4];
#pragma unroll
            for (int i = 0; i < 4; i++)
                pa[i] = KPs[(ty * 4 + i) * 64 + c];
            float4 vv = *(const float4*)&Vs[c * 64 + tx * 4];
            const float va[4] = {vv.x, vv.y, vv.z, vv.w};
#pragma unroll
            for (int i = 0; i < 4; i++)
#pragma unroll
                for (int j = 0; j < 4; j++)
                    O[i][j] = fmaf(pa[i], va[j], O[i][j]);
        }
    }

    const int b = bh >> 4;
    const int h = bh & 15;
#pragma unroll
    for (int i = 0; i < 4; i++) {
        const float inv = 1.0f / lrow[i];
        const int t = q0 + ty * 4 + i;
        float4 ov;
        ov.x = O[i][0] * inv; ov.y = O[i][1] * inv;
        ov.z = O[i][2] * inv; ov.w = O[i][3] * inv;
        *(float4*)&g_y[((size_t)b * T_DIM + t) * C_DIM + h * D_DIM + tx * 4] = ov;
    }
}

// ---------------------------------------------------------------------------
extern "C" void kernel_launch(void* const* d_in, const int* in_sizes, int n_in,
                              void* d_out, int out_size)
{
    const float* x  = (const float*)d_in[0];
    const float* Wq = (const float*)d_in[1];
    const float* bq = (const float*)d_in[2];
    const float* Wk = (const float*)d_in[3];
    const float* bk = (const float*)d_in[4];
    const float* Wv = (const float*)d_in[5];
    const float* bv = (const float*)d_in[6];
    const float* Wo = (const float*)d_in[7];
    const float* bo = (const float*)d_in[8];
    float* out = (float*)d_out;

    const int nx4 = M_ROWS * C_DIM / 4;   // 2097152
    const int nw4 = C_DIM * C_DIM / 4;    // 262144

    // 0) fp32 -> bf16 hi/lo splits for X and all weights
    split_sel_kernel<<<nx4 / 256, 256>>>(x,  0, nx4);
    split_sel_kernel<<<nw4 / 256, 256>>>(Wq, 1, nw4);
    split_sel_kernel<<<nw4 / 256, 256>>>(Wk, 2, nw4);
    split_sel_kernel<<<nw4 / 256, 256>>>(Wv, 3, nw4);
    split_sel_kernel<<<nw4 / 256, 256>>>(Wo, 4, nw4);

    // 1) QKV projections on HMMA (bf16x3) -> g_q/g_k/g_v [B,H,T,D] fp32
    {
        dim3 grid(C_DIM / 128, M_ROWS / 128, 3);
        qkv_mma_kernel<<<grid, 256>>>(bq, bk, bv);
    }

    // 2) Flash attention (fp32) -> g_y [B,T,C]
    {
        dim3 grid(T_DIM / 64, B_DIM * H_NUM);
        const float scale = 1.0f / sqrtf((float)D_DIM);
        flash_attn_kernel<<<grid, 256>>>(scale);
    }

    // 3) Split attention output, then output projection on HMMA -> d_out
    split_sel_kernel<<<nx4 / 256, 256>>>(nullptr, 5, nx4);
    {
        dim3 grid(C_DIM / 128, M_ROWS / 128, 1);
        out_mma_kernel<<<grid, 256>>>(bo, out);
    }
}

// round 9
// speedup vs baseline: 2.3931x; 1.7801x over previous
#include <cuda_runtime.h>
#include <cuda_bf16.h>
#include <cstdint>
#include <math.h>

#define B_DIM 4
#define T_DIM 2048
#define C_DIM 1024
#define H_NUM 16
#define D_DIM 64
#define M_ROWS (B_DIM * T_DIM)   // 8192

// Q pre-scale: (1/sqrt(64)) * log2(e)  -> softmax in 2^x domain
#define Q_FACTOR 0.18033688011112042f

// ---------------------------------------------------------------------------
// Scratch (device globals — no allocation allowed)
// ---------------------------------------------------------------------------
__device__ __nv_bfloat16 g_xhi[(size_t)M_ROWS * C_DIM];
__device__ __nv_bfloat16 g_xlo[(size_t)M_ROWS * C_DIM];
__device__ __nv_bfloat16 g_whi[(size_t)3 * C_DIM * C_DIM];  // Wq,Wk,Wv
__device__ __nv_bfloat16 g_wlo[(size_t)3 * C_DIM * C_DIM];
__device__ __nv_bfloat16 g_wohi[(size_t)C_DIM * C_DIM];
__device__ __nv_bfloat16 g_wolo[(size_t)C_DIM * C_DIM];

// Q/K/V in [B,H,T,D], bf16 hi/lo pairs (written by QKV GEMM epilogue)
__device__ __nv_bfloat16 g_qhi[(size_t)M_ROWS * C_DIM];
__device__ __nv_bfloat16 g_qlo[(size_t)M_ROWS * C_DIM];
__device__ __nv_bfloat16 g_khi[(size_t)M_ROWS * C_DIM];
__device__ __nv_bfloat16 g_klo[(size_t)M_ROWS * C_DIM];
__device__ __nv_bfloat16 g_vhi[(size_t)M_ROWS * C_DIM];
__device__ __nv_bfloat16 g_vlo[(size_t)M_ROWS * C_DIM];

// attention output y in [B,T,C], bf16 hi/lo (written by flash epilogue)
__device__ __nv_bfloat16 g_yhi[(size_t)M_ROWS * C_DIM];
__device__ __nv_bfloat16 g_ylo[(size_t)M_ROWS * C_DIM];

// ---------------------------------------------------------------------------
// mma.sync helpers (legacy HMMA path — works on plain sm_103 target)
// ---------------------------------------------------------------------------
__device__ __forceinline__ uint32_t smem_u32(const void* p) {
    uint32_t a;
    asm("{ .reg .u64 t; cvta.to.shared.u64 t, %1; cvt.u32.u64 %0, t; }"
        : "=r"(a) : "l"(p));
    return a;
}

__device__ __forceinline__ void ldmatrix_x4(uint32_t& r0, uint32_t& r1,
                                            uint32_t& r2, uint32_t& r3,
                                            uint32_t addr)
{
    asm volatile("ldmatrix.sync.aligned.m8n8.x4.shared.b16 {%0,%1,%2,%3}, [%4];"
                 : "=r"(r0), "=r"(r1), "=r"(r2), "=r"(r3) : "r"(addr));
}

__device__ __forceinline__ void ldmatrix_x4_trans(uint32_t& r0, uint32_t& r1,
                                                  uint32_t& r2, uint32_t& r3,
                                                  uint32_t addr)
{
    asm volatile("ldmatrix.sync.aligned.m8n8.x4.trans.shared.b16 {%0,%1,%2,%3}, [%4];"
                 : "=r"(r0), "=r"(r1), "=r"(r2), "=r"(r3) : "r"(addr));
}

__device__ __forceinline__ void mma_16816(float* c, const uint32_t* a,
                                          const uint32_t* b)
{
    asm volatile(
        "mma.sync.aligned.m16n8k16.row.col.f32.bf16.bf16.f32 "
        "{%0,%1,%2,%3}, {%4,%5,%6,%7}, {%8,%9}, {%0,%1,%2,%3};"
        : "+f"(c[0]), "+f"(c[1]), "+f"(c[2]), "+f"(c[3])
        : "r"(a[0]), "r"(a[1]), "r"(a[2]), "r"(a[3]), "r"(b[0]), "r"(b[1]));
}

// exp2 on the FMA pipe: degree-5 poly + exponent splice.  y <= 0 expected.
__device__ __forceinline__ float exp2_poly(float y) {
    y = fmaxf(y, -60.0f);
    float t = __fadd_rn(y, 12582912.0f);          // 1.5 * 2^23: round-to-int
    int   n = __float_as_int(t) - 0x4B400000;     // integer part (can be < 0)
    float f = __fsub_rn(y, __fsub_rn(t, 12582912.0f));   // frac in [-0.5, 0.5]
    float p = 0.0013333558f;
    p = fmaf(p, f, 0.0096181298f);
    p = fmaf(p, f, 0.0555041087f);
    p = fmaf(p, f, 0.2402265069f);
    p = fmaf(p, f, 0.6931471806f);
    p = fmaf(p, f, 1.0f);
    return __int_as_float(__float_as_int(p) + (n << 23));
}

// split (x,y) fp32 pair into packed bf16x2 hi and lo (residual) words
__device__ __forceinline__ void split_pack(float x, float y,
                                           uint32_t& hi, uint32_t& lo)
{
    __nv_bfloat16 hx = __float2bfloat16(x);
    __nv_bfloat16 hy = __float2bfloat16(y);
    float rx = x - __bfloat162float(hx);
    float ry = y - __bfloat162float(hy);
    __nv_bfloat162 h2; h2.x = hx; h2.y = hy;
    __nv_bfloat162 l2; l2.x = __float2bfloat16(rx); l2.y = __float2bfloat16(ry);
    hi = *(uint32_t*)&h2;
    lo = *(uint32_t*)&l2;
}

// ---------------------------------------------------------------------------
// Split fp32 -> bf16 hi/lo pair.  sel: 0=x  1..3=W(q,k,v)  4=Wo
// ---------------------------------------------------------------------------
__global__ void __launch_bounds__(256)
split_sel_kernel(const float* __restrict__ src_in, int sel, int n4)
{
    int i = blockIdx.x * blockDim.x + threadIdx.x;
    if (i >= n4) return;

    const float* src = src_in;
    __nv_bfloat16* hi;
    __nv_bfloat16* lo;
    if (sel == 0)      { hi = g_xhi;  lo = g_xlo; }
    else if (sel <= 3) { size_t o = (size_t)(sel - 1) << 20; hi = g_whi + o; lo = g_wlo + o; }
    else               { hi = g_wohi; lo = g_wolo; }

    float4 v = *(const float4*)(src + (size_t)i * 4);
    float f[4] = {v.x, v.y, v.z, v.w};
    __nv_bfloat16 h[4], l[4];
#pragma unroll
    for (int j = 0; j < 4; j++) {
        h[j] = __float2bfloat16(f[j]);
        l[j] = __float2bfloat16(f[j] - __bfloat162float(h[j]));
    }
    __nv_bfloat162 hv0 = {h[0], h[1]}, hv1 = {h[2], h[3]};
    __nv_bfloat162 lv0 = {l[0], l[1]}, lv1 = {l[2], l[3]};
    *(__nv_bfloat162*)(hi + (size_t)i * 4)     = hv0;
    *(__nv_bfloat162*)(hi + (size_t)i * 4 + 2) = hv1;
    *(__nv_bfloat162*)(lo + (size_t)i * 4)     = lv0;
    *(__nv_bfloat162*)(lo + (size_t)i * 4 + 2) = lv1;
}

// ---------------------------------------------------------------------------
// mma.sync bf16x3 NT GEMM: res[m,n] = sum_k A[m,k]*B[n,k] + bias[n]
// CTA tile 128x128, 256 threads = 8 warps, warp tile 32(M) x 64(N).
// REMAP=0: fp32 out[m*C+n].
// REMAP=1: bf16 hi/lo split of res*factor -> outhi/outlo at
//          [((b*H+h)*T+t)*D+d]  (b=m/T, t=m%T, h=n/D, d=n%D)
// ---------------------------------------------------------------------------
#define KC 32
#define LDS 40   // padded row length (bf16 elems)

template <int REMAP>
__device__ __forceinline__ void mma_gemm_body(
    const __nv_bfloat16* __restrict__ Ahi, const __nv_bfloat16* __restrict__ Alo,
    const __nv_bfloat16* __restrict__ Bhi, const __nv_bfloat16* __restrict__ Blo,
    const float* __restrict__ bias, float* __restrict__ out,
    __nv_bfloat16* __restrict__ outhi, __nv_bfloat16* __restrict__ outlo,
    float factor)
{
    __shared__ __nv_bfloat16 sAhi[128][LDS];
    __shared__ __nv_bfloat16 sAlo[128][LDS];
    __shared__ __nv_bfloat16 sBhi[128][LDS];
    __shared__ __nv_bfloat16 sBlo[128][LDS];

    const int tid  = threadIdx.x;
    const int lane = tid & 31;
    const int wid  = tid >> 5;
    const int wm   = wid & 3;    // M warp group: 32 rows
    const int wn   = wid >> 2;   // N warp group: 64 cols
    const int bm = blockIdx.y * 128;
    const int bn = blockIdx.x * 128;

    float acc[2][8][4];
#pragma unroll
    for (int i = 0; i < 2; i++)
#pragma unroll
        for (int j = 0; j < 8; j++)
#pragma unroll
            for (int c = 0; c < 4; c++) acc[i][j][c] = 0.0f;

    const int lrow = tid >> 1;
    const int lcol = (tid & 1) << 4;   // 0 or 16
    const __nv_bfloat16* gAhi = Ahi + (size_t)(bm + lrow) * C_DIM + lcol;
    const __nv_bfloat16* gAlo = Alo + (size_t)(bm + lrow) * C_DIM + lcol;
    const __nv_bfloat16* gBhi = Bhi + (size_t)(bn + lrow) * C_DIM + lcol;
    const __nv_bfloat16* gBlo = Blo + (size_t)(bn + lrow) * C_DIM + lcol;

    const int lr = lane & 7;
    const int lm = lane >> 3;          // 0..3
    const int a_row = wm * 32 + (lm & 1) * 8 + lr;
    const int a_col = (lm >> 1) * 8;
    const int b_row = wn * 64 + (lm >> 1) * 8 + lr;
    const int b_col = (lm & 1) * 8;

    const uint32_t uAhi = smem_u32(&sAhi[0][0]);
    const uint32_t uAlo = smem_u32(&sAlo[0][0]);
    const uint32_t uBhi = smem_u32(&sBhi[0][0]);
    const uint32_t uBlo = smem_u32(&sBlo[0][0]);

    for (int kc = 0; kc < C_DIM / KC; kc++) {
        const int k0 = kc * KC;
        __syncthreads();
        *(uint4*)&sAhi[lrow][lcol]     = *(const uint4*)(gAhi + k0);
        *(uint4*)&sAhi[lrow][lcol + 8] = *(const uint4*)(gAhi + k0 + 8);
        *(uint4*)&sAlo[lrow][lcol]     = *(const uint4*)(gAlo + k0);
        *(uint4*)&sAlo[lrow][lcol + 8] = *(const uint4*)(gAlo + k0 + 8);
        *(uint4*)&sBhi[lrow][lcol]     = *(const uint4*)(gBhi + k0);
        *(uint4*)&sBhi[lrow][lcol + 8] = *(const uint4*)(gBhi + k0 + 8);
        *(uint4*)&sBlo[lrow][lcol]     = *(const uint4*)(gBlo + k0);
        *(uint4*)&sBlo[lrow][lcol + 8] = *(const uint4*)(gBlo + k0 + 8);
        __syncthreads();

#pragma unroll
        for (int ks = 0; ks < KC / 16; ks++) {
            const int ko = ks * 16;

            uint32_t afh[2][4], afl[2][4];
#pragma unroll
            for (int mi = 0; mi < 2; mi++) {
                const uint32_t off =
                    (uint32_t)((a_row + mi * 16) * LDS + ko + a_col) * 2u;
                ldmatrix_x4(afh[mi][0], afh[mi][1], afh[mi][2], afh[mi][3], uAhi + off);
                ldmatrix_x4(afl[mi][0], afl[mi][1], afl[mi][2], afl[mi][3], uAlo + off);
            }

            uint32_t bfh[8][2], bfl[8][2];
#pragma unroll
            for (int ni = 0; ni < 4; ni++) {
                const uint32_t off =
                    (uint32_t)((b_row + ni * 16) * LDS + ko + b_col) * 2u;
                uint32_t r0, r1, r2, r3;
                ldmatrix_x4(r0, r1, r2, r3, uBhi + off);
                bfh[ni * 2][0] = r0; bfh[ni * 2][1] = r1;
                bfh[ni * 2 + 1][0] = r2; bfh[ni * 2 + 1][1] = r3;
                ldmatrix_x4(r0, r1, r2, r3, uBlo + off);
                bfl[ni * 2][0] = r0; bfl[ni * 2][1] = r1;
                bfl[ni * 2 + 1][0] = r2; bfl[ni * 2 + 1][1] = r3;
            }

#pragma unroll
            for (int mi = 0; mi < 2; mi++)
#pragma unroll
                for (int nj = 0; nj < 8; nj++) {
                    mma_16816(acc[mi][nj], afh[mi], bfh[nj]);
                    mma_16816(acc[mi][nj], afh[mi], bfl[nj]);
                    mma_16816(acc[mi][nj], afl[mi], bfh[nj]);
                }
        }
    }

#pragma unroll
    for (int mi = 0; mi < 2; mi++) {
#pragma unroll
        for (int nj = 0; nj < 8; nj++) {
#pragma unroll
            for (int cp = 0; cp < 2; cp++) {
                const int m = bm + wm * 32 + mi * 16 + (lane >> 2) + cp * 8;
                const int n = bn + wn * 64 + nj * 8 + (lane & 3) * 2;
                float v0 = acc[mi][nj][cp * 2 + 0] + bias[n];
                float v1 = acc[mi][nj][cp * 2 + 1] + bias[n + 1];
                if (REMAP == 0) {
                    float2 v; v.x = v0; v.y = v1;
                    *(float2*)&out[(size_t)m * C_DIM + n] = v;
                } else {
                    v0 *= factor; v1 *= factor;
                    uint32_t hw, lw;
                    split_pack(v0, v1, hw, lw);
                    const int b = m >> 11;
                    const int t = m & (T_DIM - 1);
                    const int h = n >> 6;
                    const int d = n & (D_DIM - 1);
                    const size_t idx =
                        (((size_t)(b * H_NUM + h)) * T_DIM + t) * D_DIM + d;
                    *(uint32_t*)&outhi[idx] = hw;
                    *(uint32_t*)&outlo[idx] = lw;
                }
            }
        }
    }
}

__global__ void __launch_bounds__(256, 1)
qkv_mma_kernel(const float* __restrict__ bq, const float* __restrict__ bk,
               const float* __restrict__ bv)
{
    const size_t z = blockIdx.z;
    const __nv_bfloat16* Bh = g_whi + (z << 20);
    const __nv_bfloat16* Bl = g_wlo + (z << 20);
    const float* bias;
    __nv_bfloat16 *oh, *ol;
    float factor;
    if (z == 0)      { bias = bq; oh = g_qhi; ol = g_qlo; factor = Q_FACTOR; }
    else if (z == 1) { bias = bk; oh = g_khi; ol = g_klo; factor = 1.0f; }
    else             { bias = bv; oh = g_vhi; ol = g_vlo; factor = 1.0f; }
    mma_gemm_body<1>(g_xhi, g_xlo, Bh, Bl, bias, nullptr, oh, ol, factor);
}

__global__ void __launch_bounds__(256, 1)
out_mma_kernel(const float* __restrict__ bo, float* __restrict__ out)
{
    mma_gemm_body<0>(g_yhi, g_ylo, g_wohi, g_wolo, bo, out, nullptr, nullptr, 1.0f);
}

// ---------------------------------------------------------------------------
// HMMA flash attention.  One block per (128-row q-tile, b*h), 256 threads.
// Warp w owns score rows 16w..16w+15 across the full BK=64 key tile, so
// softmax reductions stay within a warp (4-lane shfl groups).
// QK: 3-term hi/lo compensated.  PV: 3-term (P split in regs, V hi/lo).
// exp2 computed on the FMA pipe (poly), scores already in log2 domain
// (Q pre-scaled by (1/sqrt(D))*log2e in the QKV GEMM epilogue).
// Smem: 4 x [64][72] bf16 tiles (Khi,Klo,Vhi,Vlo; Q staged through first two).
// ---------------------------------------------------------------------------
__global__ void __launch_bounds__(256)
flash_mma_kernel()
{
    __shared__ __nv_bfloat16 sm[4][64][72];   // 36864 B

    const int tid  = threadIdx.x;
    const int lane = tid & 31;
    const int wid  = tid >> 5;
    const int lr = lane & 7;
    const int lm = lane >> 3;
    const int bh = blockIdx.y;
    const int q0 = blockIdx.x * 128;
    const size_t hb = (size_t)bh * T_DIM * D_DIM;

    // ---- stage Q hi/lo fragments into registers (once) ----
    uint32_t qh[4][4], ql[4][4];
    {
        __nv_bfloat16* qs = &sm[0][0][0];   // 128 rows x 72 pitch
        const int arow = wid * 16 + (lm & 1) * 8 + lr;
#pragma unroll
        for (int pass = 0; pass < 2; pass++) {
            const __nv_bfloat16* src =
                (pass == 0 ? g_qhi : g_qlo) + hb + (size_t)q0 * D_DIM;
            __syncthreads();
#pragma unroll
            for (int s = 0; s < 4; s++) {
                const int ch = s * 256 + tid;     // 0..1023
                const int row = ch >> 3, c = ch & 7;
                *(uint4*)&qs[row * 72 + c * 8] = *(const uint4*)&src[row * 64 + c * 8];
            }
            __syncthreads();
#pragma unroll
            for (int ks = 0; ks < 4; ks++) {
                uint32_t ad = smem_u32(&qs[arow * 72 + ks * 16 + (lm >> 1) * 8]);
                if (pass == 0) ldmatrix_x4(qh[ks][0], qh[ks][1], qh[ks][2], qh[ks][3], ad);
                else           ldmatrix_x4(ql[ks][0], ql[ks][1], ql[ks][2], ql[ks][3], ad);
            }
        }
    }

    float o[8][4];
#pragma unroll
    for (int j = 0; j < 8; j++)
#pragma unroll
        for (int c = 0; c < 4; c++) o[j][c] = 0.0f;
    float m0 = -1e30f, m1 = -1e30f, l0 = 0.0f, l1 = 0.0f;

    const int brow = (lm >> 1) * 8 + lr;     // QK B-frag row within 16-block
    const int bcol = (lm & 1) * 8;
    const int vcol = (lm >> 1) * 8;          // PV V-frag (trans) col-block
    const int vrow = (lm & 1) * 8 + lr;

    for (int kt = 0; kt < T_DIM / 64; kt++) {
        const int k0 = kt * 64;
        __syncthreads();
        // ---- load K/V hi/lo tiles (coalesced) ----
        {
            const __nv_bfloat16* b0 = g_khi + hb + (size_t)k0 * D_DIM;
            const __nv_bfloat16* b1 = g_klo + hb + (size_t)k0 * D_DIM;
            const __nv_bfloat16* b2 = g_vhi + hb + (size_t)k0 * D_DIM;
            const __nv_bfloat16* b3 = g_vlo + hb + (size_t)k0 * D_DIM;
#pragma unroll
            for (int s = 0; s < 2; s++) {
                const int ch = s * 256 + tid;   // 0..511
                const int row = ch >> 3, c = ch & 7;
                *(uint4*)&sm[0][row][c * 8] = *(const uint4*)&b0[row * 64 + c * 8];
                *(uint4*)&sm[1][row][c * 8] = *(const uint4*)&b1[row * 64 + c * 8];
                *(uint4*)&sm[2][row][c * 8] = *(const uint4*)&b2[row * 64 + c * 8];
                *(uint4*)&sm[3][row][c * 8] = *(const uint4*)&b3[row * 64 + c * 8];
            }
        }
        __syncthreads();

        // ---- S = Q * K^T (compensated) ----
        float sc[8][4];
#pragma unroll
        for (int j = 0; j < 8; j++)
#pragma unroll
            for (int c = 0; c < 4; c++) sc[j][c] = 0.0f;

#pragma unroll
        for (int ks = 0; ks < 4; ks++) {
            uint32_t bhf[8][2], blf[8][2];
#pragma unroll
            for (int p = 0; p < 4; p++) {
                uint32_t r0, r1, r2, r3;
                ldmatrix_x4(r0, r1, r2, r3,
                            smem_u32(&sm[0][p * 16 + brow][ks * 16 + bcol]));
                bhf[p * 2][0] = r0; bhf[p * 2][1] = r1;
                bhf[p * 2 + 1][0] = r2; bhf[p * 2 + 1][1] = r3;
                ldmatrix_x4(r0, r1, r2, r3,
                            smem_u32(&sm[1][p * 16 + brow][ks * 16 + bcol]));
                blf[p * 2][0] = r0; blf[p * 2][1] = r1;
                blf[p * 2 + 1][0] = r2; blf[p * 2 + 1][1] = r3;
            }
#pragma unroll
            for (int j = 0; j < 8; j++) {
                mma_16816(sc[j], qh[ks], bhf[j]);
                mma_16816(sc[j], qh[ks], blf[j]);
                mma_16816(sc[j], ql[ks], bhf[j]);
            }
        }

        // ---- online softmax (log2 domain) ----
        float mx0 = -1e30f, mx1 = -1e30f;
#pragma unroll
        for (int j = 0; j < 8; j++) {
            mx0 = fmaxf(mx0, fmaxf(sc[j][0], sc[j][1]));
            mx1 = fmaxf(mx1, fmaxf(sc[j][2], sc[j][3]));
        }
        mx0 = fmaxf(mx0, __shfl_xor_sync(0xffffffffu, mx0, 1));
        mx0 = fmaxf(mx0, __shfl_xor_sync(0xffffffffu, mx0, 2));
        mx1 = fmaxf(mx1, __shfl_xor_sync(0xffffffffu, mx1, 1));
        mx1 = fmaxf(mx1, __shfl_xor_sync(0xffffffffu, mx1, 2));

        const float M0 = fmaxf(m0, mx0);
        const float M1 = fmaxf(m1, mx1);
        const float c0 = exp2_poly(m0 - M0);
        const float c1 = exp2_poly(m1 - M1);
        m0 = M0; m1 = M1;

        float s0 = 0.0f, s1 = 0.0f;
#pragma unroll
        for (int j = 0; j < 8; j++) {
            sc[j][0] = exp2_poly(sc[j][0] - M0); s0 += sc[j][0];
            sc[j][1] = exp2_poly(sc[j][1] - M0); s0 += sc[j][1];
            sc[j][2] = exp2_poly(sc[j][2] - M1); s1 += sc[j][2];
            sc[j][3] = exp2_poly(sc[j][3] - M1); s1 += sc[j][3];
        }
        s0 += __shfl_xor_sync(0xffffffffu, s0, 1);
        s0 += __shfl_xor_sync(0xffffffffu, s0, 2);
        s1 += __shfl_xor_sync(0xffffffffu, s1, 1);
        s1 += __shfl_xor_sync(0xffffffffu, s1, 2);
        l0 = l0 * c0 + s0;
        l1 = l1 * c1 + s1;
#pragma unroll
        for (int j = 0; j < 8; j++) {
            o[j][0] *= c0; o[j][1] *= c0;
            o[j][2] *= c1; o[j][3] *= c1;
        }

        // ---- O += P * V (P split in regs, V hi/lo; 3-term) ----
#pragma unroll
        for (int ks = 0; ks < 4; ks++) {
            uint32_t ah[4], al[4];
            split_pack(sc[2 * ks][0],     sc[2 * ks][1],     ah[0], al[0]);
            split_pack(sc[2 * ks][2],     sc[2 * ks][3],     ah[1], al[1]);
            split_pack(sc[2 * ks + 1][0], sc[2 * ks + 1][1], ah[2], al[2]);
            split_pack(sc[2 * ks + 1][2], sc[2 * ks + 1][3], ah[3], al[3]);

            uint32_t vh[8][2], vl[8][2];
#pragma unroll
            for (int p = 0; p < 4; p++) {
                uint32_t r0, r1, r2, r3;
                ldmatrix_x4_trans(r0, r1, r2, r3,
                                  smem_u32(&sm[2][ks * 16 + vrow][p * 16 + vcol]));
                vh[p * 2][0] = r0; vh[p * 2][1] = r1;
                vh[p * 2 + 1][0] = r2; vh[p * 2 + 1][1] = r3;
                ldmatrix_x4_trans(r0, r1, r2, r3,
                                  smem_u32(&sm[3][ks * 16 + vrow][p * 16 + vcol]));
                vl[p * 2][0] = r0; vl[p * 2][1] = r1;
                vl[p * 2 + 1][0] = r2; vl[p * 2 + 1][1] = r3;
            }
#pragma unroll
            for (int j = 0; j < 8; j++) {
                mma_16816(o[j], ah, vh[j]);
                mma_16816(o[j], ah, vl[j]);
                mma_16816(o[j], al, vh[j]);
            }
        }
    }

    // ---- epilogue: normalize, split hi/lo, write y [B,T,C] as bf16 ----
    const float inv0 = 1.0f / l0;
    const float inv1 = 1.0f / l1;
    const int b = bh >> 4;
    const int h = bh & 15;
    const int r0row = q0 + wid * 16 + (lane >> 2);
#pragma unroll
    for (int j = 0; j < 8; j++) {
        const int col = h * D_DIM + j * 8 + (lane & 3) * 2;
        uint32_t hw, lw;
        split_pack(o[j][0] * inv0, o[j][1] * inv0, hw, lw);
        size_t idx = ((size_t)b * T_DIM + r0row) * C_DIM + col;
        *(uint32_t*)&g_yhi[idx] = hw;
        *(uint32_t*)&g_ylo[idx] = lw;
        split_pack(o[j][2] * inv1, o[j][3] * inv1, hw, lw);
        idx = ((size_t)b * T_DIM + r0row + 8) * C_DIM + col;
        *(uint32_t*)&g_yhi[idx] = hw;
        *(uint32_t*)&g_ylo[idx] = lw;
    }
}

// ---------------------------------------------------------------------------
extern "C" void kernel_launch(void* const* d_in, const int* in_sizes, int n_in,
                              void* d_out, int out_size)
{
    const float* x  = (const float*)d_in[0];
    const float* Wq = (const float*)d_in[1];
    const float* bq = (const float*)d_in[2];
    const float* Wk = (const float*)d_in[3];
    const float* bk = (const float*)d_in[4];
    const float* Wv = (const float*)d_in[5];
    const float* bv = (const float*)d_in[6];
    const float* Wo = (const float*)d_in[7];
    const float* bo = (const float*)d_in[8];
    float* out = (float*)d_out;

    const int nx4 = M_ROWS * C_DIM / 4;   // 2097152
    const int nw4 = C_DIM * C_DIM / 4;    // 262144

    // 0) fp32 -> bf16 hi/lo splits for X and all weights
    split_sel_kernel<<<nx4 / 256, 256>>>(x,  0, nx4);
    split_sel_kernel<<<nw4 / 256, 256>>>(Wq, 1, nw4);
    split_sel_kernel<<<nw4 / 256, 256>>>(Wk, 2, nw4);
    split_sel_kernel<<<nw4 / 256, 256>>>(Wv, 3, nw4);
    split_sel_kernel<<<nw4 / 256, 256>>>(Wo, 4, nw4);

    // 1) QKV projections on HMMA -> q/k/v bf16 hi/lo in [B,H,T,D]
    {
        dim3 grid(C_DIM / 128, M_ROWS / 128, 3);
        qkv_mma_kernel<<<grid, 256>>>(bq, bk, bv);
    }

    // 2) HMMA flash attention -> g_yhi/g_ylo [B,T,C]
    {
        dim3 grid(T_DIM / 128, B_DIM * H_NUM);
        flash_mma_kernel<<<grid, 256>>>();
    }

    // 3) Output projection on HMMA -> d_out
    {
        dim3 grid(C_DIM / 128, M_ROWS / 128, 1);
        out_mma_kernel<<<grid, 256>>>(bo, out);
    }
}

// round 12
// speedup vs baseline: 2.9404x; 1.2287x over previous
#include <cuda_runtime.h>
#include <cuda_bf16.h>
#include <cstdint>
#include <math.h>

#define B_DIM 4
#define T_DIM 2048
#define C_DIM 1024
#define H_NUM 16
#define D_DIM 64
#define M_ROWS (B_DIM * T_DIM)   // 8192

// Q pre-scale: (1/sqrt(64)) * log2(e)  -> softmax in 2^x domain
#define Q_FACTOR 0.18033688011112042f

// ---------------------------------------------------------------------------
// Scratch (device globals — no allocation allowed)
// ---------------------------------------------------------------------------
__device__ __nv_bfloat16 g_xhi[(size_t)M_ROWS * C_DIM];
__device__ __nv_bfloat16 g_xlo[(size_t)M_ROWS * C_DIM];
__device__ __nv_bfloat16 g_whi[(size_t)3 * C_DIM * C_DIM];  // Wq,Wk,Wv
__device__ __nv_bfloat16 g_wlo[(size_t)3 * C_DIM * C_DIM];
__device__ __nv_bfloat16 g_wohi[(size_t)C_DIM * C_DIM];
__device__ __nv_bfloat16 g_wolo[(size_t)C_DIM * C_DIM];

// Q/K/V in [B,H,T,D], bf16 hi/lo pairs (written by QKV GEMM epilogue)
__device__ __nv_bfloat16 g_qhi[(size_t)M_ROWS * C_DIM];
__device__ __nv_bfloat16 g_qlo[(size_t)M_ROWS * C_DIM];
__device__ __nv_bfloat16 g_khi[(size_t)M_ROWS * C_DIM];
__device__ __nv_bfloat16 g_klo[(size_t)M_ROWS * C_DIM];
__device__ __nv_bfloat16 g_vhi[(size_t)M_ROWS * C_DIM];
__device__ __nv_bfloat16 g_vlo[(size_t)M_ROWS * C_DIM];

// attention output y in [B,T,C], bf16 hi/lo (written by flash epilogue)
__device__ __nv_bfloat16 g_yhi[(size_t)M_ROWS * C_DIM];
__device__ __nv_bfloat16 g_ylo[(size_t)M_ROWS * C_DIM];

// ---------------------------------------------------------------------------
// PTX helpers
// ---------------------------------------------------------------------------
__device__ __forceinline__ uint32_t smem_u32(const void* p) {
    uint32_t a;
    asm("{ .reg .u64 t; cvta.to.shared.u64 t, %1; cvt.u32.u64 %0, t; }"
        : "=r"(a) : "l"(p));
    return a;
}

__device__ __forceinline__ void cp_async16(uint32_t dst, const void* src) {
    asm volatile("cp.async.cg.shared.global [%0], [%1], 16;"
                 :: "r"(dst), "l"(src) : "memory");
}
#define CP_COMMIT() asm volatile("cp.async.commit_group;" ::: "memory")
#define CP_WAIT0()  asm volatile("cp.async.wait_group 0;" ::: "memory")
#define CP_WAIT1()  asm volatile("cp.async.wait_group 1;" ::: "memory")

__device__ __forceinline__ void ldmatrix_x4(uint32_t& r0, uint32_t& r1,
                                            uint32_t& r2, uint32_t& r3,
                                            uint32_t addr)
{
    asm volatile("ldmatrix.sync.aligned.m8n8.x4.shared.b16 {%0,%1,%2,%3}, [%4];"
                 : "=r"(r0), "=r"(r1), "=r"(r2), "=r"(r3) : "r"(addr));
}

__device__ __forceinline__ void ldmatrix_x4_trans(uint32_t& r0, uint32_t& r1,
                                                  uint32_t& r2, uint32_t& r3,
                                                  uint32_t addr)
{
    asm volatile("ldmatrix.sync.aligned.m8n8.x4.trans.shared.b16 {%0,%1,%2,%3}, [%4];"
                 : "=r"(r0), "=r"(r1), "=r"(r2), "=r"(r3) : "r"(addr));
}

__device__ __forceinline__ void mma_16816(float* c, const uint32_t* a,
                                          const uint32_t* b)
{
    asm volatile(
        "mma.sync.aligned.m16n8k16.row.col.f32.bf16.bf16.f32 "
        "{%0,%1,%2,%3}, {%4,%5,%6,%7}, {%8,%9}, {%0,%1,%2,%3};"
        : "+f"(c[0]), "+f"(c[1]), "+f"(c[2]), "+f"(c[3])
        : "r"(a[0]), "r"(a[1]), "r"(a[2]), "r"(a[3]), "r"(b[0]), "r"(b[1]));
}

// exp2 on the FMA pipe: degree-5 poly + exponent splice.  y <= 0 expected.
__device__ __forceinline__ float exp2_poly(float y) {
    y = fmaxf(y, -60.0f);
    float t = __fadd_rn(y, 12582912.0f);          // 1.5 * 2^23: round-to-int
    int   n = __float_as_int(t) - 0x4B400000;     // integer part (can be < 0)
    float f = __fsub_rn(y, __fsub_rn(t, 12582912.0f));   // frac in [-0.5, 0.5]
    float p = 0.0013333558f;
    p = fmaf(p, f, 0.0096181298f);
    p = fmaf(p, f, 0.0555041087f);
    p = fmaf(p, f, 0.2402265069f);
    p = fmaf(p, f, 0.6931471806f);
    p = fmaf(p, f, 1.0f);
    return __int_as_float(__float_as_int(p) + (n << 23));
}

// split (x,y) fp32 pair into packed bf16x2 hi and lo (residual) words
__device__ __forceinline__ void split_pack(float x, float y,
                                           uint32_t& hi, uint32_t& lo)
{
    __nv_bfloat16 hx = __float2bfloat16(x);
    __nv_bfloat16 hy = __float2bfloat16(y);
    float rx = x - __bfloat162float(hx);
    float ry = y - __bfloat162float(hy);
    __nv_bfloat162 h2; h2.x = hx; h2.y = hy;
    __nv_bfloat162 l2; l2.x = __float2bfloat16(rx); l2.y = __float2bfloat16(ry);
    hi = *(uint32_t*)&h2;
    lo = *(uint32_t*)&l2;
}

// ---------------------------------------------------------------------------
// fp32 -> bf16 hi/lo splits
// ---------------------------------------------------------------------------
__device__ __forceinline__ void split_body(const float* __restrict__ src,
                                           __nv_bfloat16* __restrict__ hi,
                                           __nv_bfloat16* __restrict__ lo,
                                           int i)
{
    float4 v = *(const float4*)(src + (size_t)i * 4);
    float f[4] = {v.x, v.y, v.z, v.w};
    __nv_bfloat16 h[4], l[4];
#pragma unroll
    for (int j = 0; j < 4; j++) {
        h[j] = __float2bfloat16(f[j]);
        l[j] = __float2bfloat16(f[j] - __bfloat162float(h[j]));
    }
    __nv_bfloat162 hv0 = {h[0], h[1]}, hv1 = {h[2], h[3]};
    __nv_bfloat162 lv0 = {l[0], l[1]}, lv1 = {l[2], l[3]};
    *(__nv_bfloat162*)(hi + (size_t)i * 4)     = hv0;
    *(__nv_bfloat162*)(hi + (size_t)i * 4 + 2) = hv1;
    *(__nv_bfloat162*)(lo + (size_t)i * 4)     = lv0;
    *(__nv_bfloat162*)(lo + (size_t)i * 4 + 2) = lv1;
}

__global__ void __launch_bounds__(256)
split_x_kernel(const float* __restrict__ x, int n4)
{
    int i = blockIdx.x * blockDim.x + threadIdx.x;
    if (i < n4) split_body(x, g_xhi, g_xlo, i);
}

__global__ void __launch_bounds__(256)
split_w_kernel(const float* __restrict__ Wq, const float* __restrict__ Wk,
               const float* __restrict__ Wv, const float* __restrict__ Wo,
               int n4)
{
    int i = blockIdx.x * blockDim.x + threadIdx.x;
    if (i >= n4) return;
    const int z = blockIdx.y;
    const float* src = (z == 0) ? Wq : (z == 1) ? Wk : (z == 2) ? Wv : Wo;
    __nv_bfloat16* hi = (z < 3) ? g_whi + ((size_t)z << 20) : g_wohi;
    __nv_bfloat16* lo = (z < 3) ? g_wlo + ((size_t)z << 20) : g_wolo;
    split_body(src, hi, lo, i);
}

// ---------------------------------------------------------------------------
// mma.sync bf16x3 NT GEMM with 2-stage cp.async pipeline.
// res[m,n] = sum_k A[m,k]*B[n,k] + bias[n]
// CTA tile 128x128, 256 threads = 8 warps, warp tile 32(M) x 64(N).
// Dynamic smem: 2 stages x 4 tiles x [128][40] bf16 = 81920 B.
// REMAP=0: fp32 out[m*C+n].
// REMAP=1: bf16 hi/lo split of res*factor -> outhi/outlo at [((b*H+h)*T+t)*D+d]
// ---------------------------------------------------------------------------
#define KC 32
#define LDSG 40
#define GT_BYTES (128 * LDSG * 2)   // 10240 per tile
#define GS_BYTES (4 * GT_BYTES)     // 40960 per stage
#define GEMM_SMEM (2 * GS_BYTES)    // 81920

template <int REMAP>
__device__ __forceinline__ void mma_gemm_body(
    const __nv_bfloat16* __restrict__ Ahi, const __nv_bfloat16* __restrict__ Alo,
    const __nv_bfloat16* __restrict__ Bhi, const __nv_bfloat16* __restrict__ Blo,
    const float* __restrict__ bias, float* __restrict__ out,
    __nv_bfloat16* __restrict__ outhi, __nv_bfloat16* __restrict__ outlo,
    float factor)
{
    extern __shared__ __align__(16) uint8_t dsm[];
    const uint32_t sbase = smem_u32(dsm);

    const int tid  = threadIdx.x;
    const int lane = tid & 31;
    const int wid  = tid >> 5;
    const int wm   = wid & 3;    // M warp group: 32 rows
    const int wn   = wid >> 2;   // N warp group: 64 cols
    const int bm = blockIdx.y * 128;
    const int bn = blockIdx.x * 128;

    float acc[2][8][4];
#pragma unroll
    for (int i = 0; i < 2; i++)
#pragma unroll
        for (int j = 0; j < 8; j++)
#pragma unroll
            for (int c = 0; c < 4; c++) acc[i][j][c] = 0.0f;

    const int lrow = tid >> 1;
    const int lcol = (tid & 1) << 4;   // 0 or 16
    const __nv_bfloat16* gAhi = Ahi + (size_t)(bm + lrow) * C_DIM + lcol;
    const __nv_bfloat16* gAlo = Alo + (size_t)(bm + lrow) * C_DIM + lcol;
    const __nv_bfloat16* gBhi = Bhi + (size_t)(bn + lrow) * C_DIM + lcol;
    const __nv_bfloat16* gBlo = Blo + (size_t)(bn + lrow) * C_DIM + lcol;
    const uint32_t doff = (uint32_t)(lrow * LDSG + lcol) * 2u;

    auto issue = [&](int s, int k0) {
        const uint32_t st = sbase + (uint32_t)s * GS_BYTES + doff;
        cp_async16(st + 0 * GT_BYTES,      gAhi + k0);
        cp_async16(st + 0 * GT_BYTES + 16, gAhi + k0 + 8);
        cp_async16(st + 1 * GT_BYTES,      gAlo + k0);
        cp_async16(st + 1 * GT_BYTES + 16, gAlo + k0 + 8);
        cp_async16(st + 2 * GT_BYTES,      gBhi + k0);
        cp_async16(st + 2 * GT_BYTES + 16, gBhi + k0 + 8);
        cp_async16(st + 3 * GT_BYTES,      gBlo + k0);
        cp_async16(st + 3 * GT_BYTES + 16, gBlo + k0 + 8);
    };

    const int lr = lane & 7;
    const int lm = lane >> 3;          // 0..3
    const int a_row = wm * 32 + (lm & 1) * 8 + lr;
    const int a_col = (lm >> 1) * 8;
    const int b_row = wn * 64 + (lm >> 1) * 8 + lr;
    const int b_col = (lm & 1) * 8;

    const int NK = C_DIM / KC;   // 32
    issue(0, 0); CP_COMMIT();

    for (int kc = 0; kc < NK; kc++) {
        if (kc + 1 < NK) { issue((kc + 1) & 1, (kc + 1) * KC); CP_COMMIT(); CP_WAIT1(); }
        else             { CP_WAIT0(); }
        __syncthreads();

        const uint32_t uAhi = sbase + (uint32_t)(kc & 1) * GS_BYTES;
        const uint32_t uAlo = uAhi + GT_BYTES;
        const uint32_t uBhi = uAhi + 2 * GT_BYTES;
        const uint32_t uBlo = uAhi + 3 * GT_BYTES;

#pragma unroll
        for (int ks = 0; ks < KC / 16; ks++) {
            const int ko = ks * 16;

            uint32_t afh[2][4], afl[2][4];
#pragma unroll
            for (int mi = 0; mi < 2; mi++) {
                const uint32_t off =
                    (uint32_t)((a_row + mi * 16) * LDSG + ko + a_col) * 2u;
                ldmatrix_x4(afh[mi][0], afh[mi][1], afh[mi][2], afh[mi][3], uAhi + off);
                ldmatrix_x4(afl[mi][0], afl[mi][1], afl[mi][2], afl[mi][3], uAlo + off);
            }

            uint32_t bfh[8][2], bfl[8][2];
#pragma unroll
            for (int ni = 0; ni < 4; ni++) {
                const uint32_t off =
                    (uint32_t)((b_row + ni * 16) * LDSG + ko + b_col) * 2u;
                uint32_t r0, r1, r2, r3;
                ldmatrix_x4(r0, r1, r2, r3, uBhi + off);
                bfh[ni * 2][0] = r0; bfh[ni * 2][1] = r1;
                bfh[ni * 2 + 1][0] = r2; bfh[ni * 2 + 1][1] = r3;
                ldmatrix_x4(r0, r1, r2, r3, uBlo + off);
                bfl[ni * 2][0] = r0; bfl[ni * 2][1] = r1;
                bfl[ni * 2 + 1][0] = r2; bfl[ni * 2 + 1][1] = r3;
            }

#pragma unroll
            for (int mi = 0; mi < 2; mi++)
#pragma unroll
                for (int nj = 0; nj < 8; nj++) {
                    mma_16816(acc[mi][nj], afh[mi], bfh[nj]);
                    mma_16816(acc[mi][nj], afh[mi], bfl[nj]);
                    mma_16816(acc[mi][nj], afl[mi], bfh[nj]);
                }
        }
        __syncthreads();
    }

#pragma unroll
    for (int mi = 0; mi < 2; mi++) {
#pragma unroll
        for (int nj = 0; nj < 8; nj++) {
#pragma unroll
            for (int cp = 0; cp < 2; cp++) {
                const int m = bm + wm * 32 + mi * 16 + (lane >> 2) + cp * 8;
                const int n = bn + wn * 64 + nj * 8 + (lane & 3) * 2;
                float v0 = acc[mi][nj][cp * 2 + 0] + bias[n];
                float v1 = acc[mi][nj][cp * 2 + 1] + bias[n + 1];
                if (REMAP == 0) {
                    float2 v; v.x = v0; v.y = v1;
                    *(float2*)&out[(size_t)m * C_DIM + n] = v;
                } else {
                    v0 *= factor; v1 *= factor;
                    uint32_t hw, lw;
                    split_pack(v0, v1, hw, lw);
                    const int b = m >> 11;
                    const int t = m & (T_DIM - 1);
                    const int h = n >> 6;
                    const int d = n & (D_DIM - 1);
                    const size_t idx =
                        (((size_t)(b * H_NUM + h)) * T_DIM + t) * D_DIM + d;
                    *(uint32_t*)&outhi[idx] = hw;
                    *(uint32_t*)&outlo[idx] = lw;
                }
            }
        }
    }
}

__global__ void __launch_bounds__(256, 1)
qkv_mma_kernel(const float* __restrict__ bq, const float* __restrict__ bk,
               const float* __restrict__ bv)
{
    const size_t z = blockIdx.z;
    const __nv_bfloat16* Bh = g_whi + (z << 20);
    const __nv_bfloat16* Bl = g_wlo + (z << 20);
    const float* bias;
    __nv_bfloat16 *oh, *ol;
    float factor;
    if (z == 0)      { bias = bq; oh = g_qhi; ol = g_qlo; factor = Q_FACTOR; }
    else if (z == 1) { bias = bk; oh = g_khi; ol = g_klo; factor = 1.0f; }
    else             { bias = bv; oh = g_vhi; ol = g_vlo; factor = 1.0f; }
    mma_gemm_body<1>(g_xhi, g_xlo, Bh, Bl, bias, nullptr, oh, ol, factor);
}

__global__ void __launch_bounds__(256, 1)
out_mma_kernel(const float* __restrict__ bo, float* __restrict__ out)
{
    mma_gemm_body<0>(g_yhi, g_ylo, g_wohi, g_wolo, bo, out, nullptr, nullptr, 1.0f);
}

// ---------------------------------------------------------------------------
// HMMA flash attention, 2-stage cp.async pipeline on the K/V tiles.
// One block per (128-row q-tile, b*h), 256 threads.  Warp w owns score rows
// 16w..16w+15 over the BK=64 key tile (softmax reductions intra-warp).
// QK: 3-term hi/lo compensated.  PV: 3-term (P split in regs, V hi/lo).
// Dynamic smem: 2 stages x 4 tiles x [64][72] bf16 = 73728 B (Q staged
// through stage area before the main loop).
// ---------------------------------------------------------------------------
#define FT_BYTES (64 * 72 * 2)     // 9216 per tile
#define FS_BYTES (4 * FT_BYTES)    // 36864 per stage
#define FLASH_SMEM (2 * FS_BYTES)  // 73728

__global__ void __launch_bounds__(256, 1)
flash_mma_kernel()
{
    extern __shared__ __align__(16) uint8_t fdsm[];
    const uint32_t sbase = smem_u32(fdsm);

    const int tid  = threadIdx.x;
    const int lane = tid & 31;
    const int wid  = tid >> 5;
    const int lr = lane & 7;
    const int lm = lane >> 3;
    const int bh = blockIdx.y;
    const int q0 = blockIdx.x * 128;
    const size_t hb = (size_t)bh * T_DIM * D_DIM;

    // ---- stage Q hi/lo fragments into registers (once) ----
    uint32_t qh[4][4], ql[4][4];
    {
        __nv_bfloat16* qs = (__nv_bfloat16*)fdsm;   // 128 rows x 72 pitch
        const int arow = wid * 16 + (lm & 1) * 8 + lr;
#pragma unroll
        for (int pass = 0; pass < 2; pass++) {
            const __nv_bfloat16* src =
                (pass == 0 ? g_qhi : g_qlo) + hb + (size_t)q0 * D_DIM;
            __syncthreads();
#pragma unroll
            for (int s = 0; s < 4; s++) {
                const int ch = s * 256 + tid;     // 0..1023
                const int row = ch >> 3, c = ch & 7;
                *(uint4*)&qs[row * 72 + c * 8] = *(const uint4*)&src[row * 64 + c * 8];
            }
            __syncthreads();
#pragma unroll
            for (int ks = 0; ks < 4; ks++) {
                uint32_t ad = smem_u32(&qs[arow * 72 + ks * 16 + (lm >> 1) * 8]);
                if (pass == 0) ldmatrix_x4(qh[ks][0], qh[ks][1], qh[ks][2], qh[ks][3], ad);
                else           ldmatrix_x4(ql[ks][0], ql[ks][1], ql[ks][2], ql[ks][3], ad);
            }
        }
        __syncthreads();   // all fragment reads done before cp.async overwrites
    }

    // cp.async issue of one K/V tile-set (2 x 16B chunks per tile per thread)
    const int c_row = tid >> 3;          // 0..31  (+32 on second sub-pass)
    const int c_c   = (tid & 7) * 16;    // byte col offset (8 chunks of 16B)
    auto fissue = [&](int s, int k0) {
        const __nv_bfloat16* b0 = g_khi + hb + (size_t)k0 * D_DIM;
        const __nv_bfloat16* b1 = g_klo + hb + (size_t)k0 * D_DIM;
        const __nv_bfloat16* b2 = g_vhi + hb + (size_t)k0 * D_DIM;
        const __nv_bfloat16* b3 = g_vlo + hb + (size_t)k0 * D_DIM;
        const uint32_t st = sbase + (uint32_t)s * FS_BYTES;
#pragma unroll
        for (int ss = 0; ss < 2; ss++) {
            const int row = c_row + ss * 32;
            const uint32_t doff = (uint32_t)(row * 144) + (uint32_t)c_c;
            const size_t soff = (size_t)row * 64 + (c_c >> 1);
            cp_async16(st + 0 * FT_BYTES + doff, b0 + soff);
            cp_async16(st + 1 * FT_BYTES + doff, b1 + soff);
            cp_async16(st + 2 * FT_BYTES + doff, b2 + soff);
            cp_async16(st + 3 * FT_BYTES + doff, b3 + soff);
        }
    };

    float o[8][4];
#pragma unroll
    for (int j = 0; j < 8; j++)
#pragma unroll
        for (int c = 0; c < 4; c++) o[j][c] = 0.0f;
    float m0 = -1e30f, m1 = -1e30f, l0 = 0.0f, l1 = 0.0f;

    const int brow = (lm >> 1) * 8 + lr;     // QK B-frag row within 16-block
    const int bcol = (lm & 1) * 8;
    const int vcol = (lm >> 1) * 8;          // PV V-frag (trans) col-block
    const int vrow = (lm & 1) * 8 + lr;

    const int NT = T_DIM / 64;   // 32
    fissue(0, 0); CP_COMMIT();

    for (int kt = 0; kt < NT; kt++) {
        if (kt + 1 < NT) { fissue((kt + 1) & 1, (kt + 1) * 64); CP_COMMIT(); CP_WAIT1(); }
        else             { CP_WAIT0(); }
        __syncthreads();

        const uint32_t uKhi = sbase + (uint32_t)(kt & 1) * FS_BYTES;
        const uint32_t uKlo = uKhi + FT_BYTES;
        const uint32_t uVhi = uKhi + 2 * FT_BYTES;
        const uint32_t uVlo = uKhi + 3 * FT_BYTES;

        // ---- S = Q * K^T (compensated) ----
        float sc[8][4];
#pragma unroll
        for (int j = 0; j < 8; j++)
#pragma unroll
            for (int c = 0; c < 4; c++) sc[j][c] = 0.0f;

#pragma unroll
        for (int ks = 0; ks < 4; ks++) {
            uint32_t bhf[8][2], blf[8][2];
#pragma unroll
            for (int p = 0; p < 4; p++) {
                const uint32_t off =
                    (uint32_t)((p * 16 + brow) * 72 + ks * 16 + bcol) * 2u;
                uint32_t r0, r1, r2, r3;
                ldmatrix_x4(r0, r1, r2, r3, uKhi + off);
                bhf[p * 2][0] = r0; bhf[p * 2][1] = r1;
                bhf[p * 2 + 1][0] = r2; bhf[p * 2 + 1][1] = r3;
                ldmatrix_x4(r0, r1, r2, r3, uKlo + off);
                blf[p * 2][0] = r0; blf[p * 2][1] = r1;
                blf[p * 2 + 1][0] = r2; blf[p * 2 + 1][1] = r3;
            }
#pragma unroll
            for (int j = 0; j < 8; j++) {
                mma_16816(sc[j], qh[ks], bhf[j]);
                mma_16816(sc[j], qh[ks], blf[j]);
                mma_16816(sc[j], ql[ks], bhf[j]);
            }
        }

        // ---- online softmax (log2 domain) ----
        float mx0 = -1e30f, mx1 = -1e30f;
#pragma unroll
        for (int j = 0; j < 8; j++) {
            mx0 = fmaxf(mx0, fmaxf(sc[j][0], sc[j][1]));
            mx1 = fmaxf(mx1, fmaxf(sc[j][2], sc[j][3]));
        }
        mx0 = fmaxf(mx0, __shfl_xor_sync(0xffffffffu, mx0, 1));
        mx0 = fmaxf(mx0, __shfl_xor_sync(0xffffffffu, mx0, 2));
        mx1 = fmaxf(mx1, __shfl_xor_sync(0xffffffffu, mx1, 1));
        mx1 = fmaxf(mx1, __shfl_xor_sync(0xffffffffu, mx1, 2));

        const float M0 = fmaxf(m0, mx0);
        const float M1 = fmaxf(m1, mx1);
        const float c0 = exp2_poly(m0 - M0);
        const float c1 = exp2_poly(m1 - M1);
        m0 = M0; m1 = M1;

        float s0 = 0.0f, s1 = 0.0f;
#pragma unroll
        for (int j = 0; j < 8; j++) {
            sc[j][0] = exp2_poly(sc[j][0] - M0); s0 += sc[j][0];
            sc[j][1] = exp2_poly(sc[j][1] - M0); s0 += sc[j][1];
            sc[j][2] = exp2_poly(sc[j][2] - M1); s1 += sc[j][2];
            sc[j][3] = exp2_poly(sc[j][3] - M1); s1 += sc[j][3];
        }
        s0 += __shfl_xor_sync(0xffffffffu, s0, 1);
        s0 += __shfl_xor_sync(0xffffffffu, s0, 2);
        s1 += __shfl_xor_sync(0xffffffffu, s1, 1);
        s1 += __shfl_xor_sync(0xffffffffu, s1, 2);
        l0 = l0 * c0 + s0;
        l1 = l1 * c1 + s1;
#pragma unroll
        for (int j = 0; j < 8; j++) {
            o[j][0] *= c0; o[j][1] *= c0;
            o[j][2] *= c1; o[j][3] *= c1;
        }

        // ---- O += P * V (P split in regs, V hi/lo; 3-term) ----
#pragma unroll
        for (int ks = 0; ks < 4; ks++) {
            uint32_t ah[4], al[4];
            split_pack(sc[2 * ks][0],     sc[2 * ks][1],     ah[0], al[0]);
            split_pack(sc[2 * ks][2],     sc[2 * ks][3],     ah[1], al[1]);
            split_pack(sc[2 * ks + 1][0], sc[2 * ks + 1][1], ah[2], al[2]);
            split_pack(sc[2 * ks + 1][2], sc[2 * ks + 1][3], ah[3], al[3]);

            uint32_t vh[8][2], vl[8][2];
#pragma unroll
            for (int p = 0; p < 4; p++) {
                const uint32_t off =
                    (uint32_t)((ks * 16 + vrow) * 72 + p * 16 + vcol) * 2u;
                uint32_t r0, r1, r2, r3;
                ldmatrix_x4_trans(r0, r1, r2, r3, uVhi + off);
                vh[p * 2][0] = r0; vh[p * 2][1] = r1;
                vh[p * 2 + 1][0] = r2; vh[p * 2 + 1][1] = r3;
                ldmatrix_x4_trans(r0, r1, r2, r3, uVlo + off);
                vl[p * 2][0] = r0; vl[p * 2][1] = r1;
                vl[p * 2 + 1][0] = r2; vl[p * 2 + 1][1] = r3;
            }
#pragma unroll
            for (int j = 0; j < 8; j++) {
                mma_16816(o[j], ah, vh[j]);
                mma_16816(o[j], ah, vl[j]);
                mma_16816(o[j], al, vh[j]);
            }
        }
        __syncthreads();
    }

    // ---- epilogue: normalize, split hi/lo, write y [B,T,C] as bf16 ----
    const float inv0 = 1.0f / l0;
    const float inv1 = 1.0f / l1;
    const int b = bh >> 4;
    const int h = bh & 15;
    const int r0row = q0 + wid * 16 + (lane >> 2);
#pragma unroll
    for (int j = 0; j < 8; j++) {
        const int col = h * D_DIM + j * 8 + (lane & 3) * 2;
        uint32_t hw, lw;
        split_pack(o[j][0] * inv0, o[j][1] * inv0, hw, lw);
        size_t idx = ((size_t)b * T_DIM + r0row) * C_DIM + col;
        *(uint32_t*)&g_yhi[idx] = hw;
        *(uint32_t*)&g_ylo[idx] = lw;
        split_pack(o[j][2] * inv1, o[j][3] * inv1, hw, lw);
        idx = ((size_t)b * T_DIM + r0row + 8) * C_DIM + col;
        *(uint32_t*)&g_yhi[idx] = hw;
        *(uint32_t*)&g_ylo[idx] = lw;
    }
}

// ---------------------------------------------------------------------------
extern "C" void kernel_launch(void* const* d_in, const int* in_sizes, int n_in,
                              void* d_out, int out_size)
{
    const float* x  = (const float*)d_in[0];
    const float* Wq = (const float*)d_in[1];
    const float* bq = (const float*)d_in[2];
    const float* Wk = (const float*)d_in[3];
    const float* bk = (const float*)d_in[4];
    const float* Wv = (const float*)d_in[5];
    const float* bv = (const float*)d_in[6];
    const float* Wo = (const float*)d_in[7];
    const float* bo = (const float*)d_in[8];
    float* out = (float*)d_out;

    // Host-side attribute sets (non-stream APIs; legal under graph capture)
    cudaFuncSetAttribute(qkv_mma_kernel,
                         cudaFuncAttributeMaxDynamicSharedMemorySize, GEMM_SMEM);
    cudaFuncSetAttribute(out_mma_kernel,
                         cudaFuncAttributeMaxDynamicSharedMemorySize, GEMM_SMEM);
    cudaFuncSetAttribute(flash_mma_kernel,
                         cudaFuncAttributeMaxDynamicSharedMemorySize, FLASH_SMEM);

    const int nx4 = M_ROWS * C_DIM / 4;   // 2097152
    const int nw4 = C_DIM * C_DIM / 4;    // 262144

    // 0) fp32 -> bf16 hi/lo splits for X and all weights
    split_x_kernel<<<nx4 / 256, 256>>>(x, nx4);
    {
        dim3 grid(nw4 / 256, 4);
        split_w_kernel<<<grid, 256>>>(Wq, Wk, Wv, Wo, nw4);
    }

    // 1) QKV projections on HMMA -> q/k/v bf16 hi/lo in [B,H,T,D]
    {
        dim3 grid(C_DIM / 128, M_ROWS / 128, 3);
        qkv_mma_kernel<<<grid, 256, GEMM_SMEM>>>(bq, bk, bv);
    }

    // 2) HMMA flash attention -> g_yhi/g_ylo [B,T,C]
    {
        dim3 grid(T_DIM / 128, B_DIM * H_NUM);
        flash_mma_kernel<<<grid, 256, FLASH_SMEM>>>();
    }

    // 3) Output projection on HMMA -> d_out
    {
        dim3 grid(C_DIM / 128, M_ROWS / 128, 1);
        out_mma_kernel<<<grid, 256, GEMM_SMEM>>>(bo, out);
    }
}

// round 14
// speedup vs baseline: 3.3117x; 1.1263x over previous
#include <cuda_runtime.h>
#include <cuda_bf16.h>
#include <cstdint>
#include <math.h>

#define B_DIM 4
#define T_DIM 2048
#define C_DIM 1024
#define H_NUM 16
#define D_DIM 64
#define M_ROWS (B_DIM * T_DIM)   // 8192

// Q pre-scale: (1/sqrt(64)) * log2(e)  -> softmax in 2^x domain
#define Q_FACTOR 0.18033688011112042f

// ---------------------------------------------------------------------------
// Scratch (device globals — no allocation allowed)
// ---------------------------------------------------------------------------
__device__ __nv_bfloat16 g_xhi[(size_t)M_ROWS * C_DIM];
__device__ __nv_bfloat16 g_xlo[(size_t)M_ROWS * C_DIM];
__device__ __nv_bfloat16 g_whi[(size_t)3 * C_DIM * C_DIM];  // Wq,Wk,Wv
__device__ __nv_bfloat16 g_wlo[(size_t)3 * C_DIM * C_DIM];
__device__ __nv_bfloat16 g_wohi[(size_t)C_DIM * C_DIM];
__device__ __nv_bfloat16 g_wolo[(size_t)C_DIM * C_DIM];

__device__ __nv_bfloat16 g_qhi[(size_t)M_ROWS * C_DIM];
__device__ __nv_bfloat16 g_qlo[(size_t)M_ROWS * C_DIM];
__device__ __nv_bfloat16 g_khi[(size_t)M_ROWS * C_DIM];
__device__ __nv_bfloat16 g_klo[(size_t)M_ROWS * C_DIM];
__device__ __nv_bfloat16 g_vhi[(size_t)M_ROWS * C_DIM];
__device__ __nv_bfloat16 g_vlo[(size_t)M_ROWS * C_DIM];

__device__ __nv_bfloat16 g_yhi[(size_t)M_ROWS * C_DIM];
__device__ __nv_bfloat16 g_ylo[(size_t)M_ROWS * C_DIM];

// ---------------------------------------------------------------------------
// PTX helpers
// ---------------------------------------------------------------------------
__device__ __forceinline__ uint32_t smem_u32(const void* p) {
    uint32_t a;
    asm("{ .reg .u64 t; cvta.to.shared.u64 t, %1; cvt.u32.u64 %0, t; }"
        : "=r"(a) : "l"(p));
    return a;
}

__device__ __forceinline__ void cp_async16(uint32_t dst, const void* src) {
    asm volatile("cp.async.cg.shared.global [%0], [%1], 16;"
                 :: "r"(dst), "l"(src) : "memory");
}
#define CP_COMMIT() asm volatile("cp.async.commit_group;" ::: "memory")
#define CP_WAIT0()  asm volatile("cp.async.wait_group 0;" ::: "memory")
#define CP_WAIT1()  asm volatile("cp.async.wait_group 1;" ::: "memory")

__device__ __forceinline__ void ldmatrix_x4(uint32_t& r0, uint32_t& r1,
                                            uint32_t& r2, uint32_t& r3,
                                            uint32_t addr)
{
    asm volatile("ldmatrix.sync.aligned.m8n8.x4.shared.b16 {%0,%1,%2,%3}, [%4];"
                 : "=r"(r0), "=r"(r1), "=r"(r2), "=r"(r3) : "r"(addr));
}

__device__ __forceinline__ void ldmatrix_x4_trans(uint32_t& r0, uint32_t& r1,
                                                  uint32_t& r2, uint32_t& r3,
                                                  uint32_t addr)
{
    asm volatile("ldmatrix.sync.aligned.m8n8.x4.trans.shared.b16 {%0,%1,%2,%3}, [%4];"
                 : "=r"(r0), "=r"(r1), "=r"(r2), "=r"(r3) : "r"(addr));
}

__device__ __forceinline__ void mma_16816(float* c, const uint32_t* a,
                                          const uint32_t* b)
{
    asm volatile(
        "mma.sync.aligned.m16n8k16.row.col.f32.bf16.bf16.f32 "
        "{%0,%1,%2,%3}, {%4,%5,%6,%7}, {%8,%9}, {%0,%1,%2,%3};"
        : "+f"(c[0]), "+f"(c[1]), "+f"(c[2]), "+f"(c[3])
        : "r"(a[0]), "r"(a[1]), "r"(a[2]), "r"(a[3]), "r"(b[0]), "r"(b[1]));
}

// exp2 on the FMA pipe: degree-5 poly + exponent splice.  y <= 0 expected.
__device__ __forceinline__ float exp2_poly(float y) {
    y = fmaxf(y, -60.0f);
    float t = __fadd_rn(y, 12582912.0f);          // 1.5 * 2^23: round-to-int
    int   n = __float_as_int(t) - 0x4B400000;     // integer part (can be < 0)
    float f = __fsub_rn(y, __fsub_rn(t, 12582912.0f));   // frac in [-0.5, 0.5]
    float p = 0.0013333558f;
    p = fmaf(p, f, 0.0096181298f);
    p = fmaf(p, f, 0.0555041087f);
    p = fmaf(p, f, 0.2402265069f);
    p = fmaf(p, f, 0.6931471806f);
    p = fmaf(p, f, 1.0f);
    return __int_as_float(__float_as_int(p) + (n << 23));
}

// split (x,y) fp32 pair into packed bf16x2 hi and lo (residual) words
__device__ __forceinline__ void split_pack(float x, float y,
                                           uint32_t& hi, uint32_t& lo)
{
    __nv_bfloat16 hx = __float2bfloat16(x);
    __nv_bfloat16 hy = __float2bfloat16(y);
    float rx = x - __bfloat162float(hx);
    float ry = y - __bfloat162float(hy);
    __nv_bfloat162 h2; h2.x = hx; h2.y = hy;
    __nv_bfloat162 l2; l2.x = __float2bfloat16(rx); l2.y = __float2bfloat16(ry);
    hi = *(uint32_t*)&h2;
    lo = *(uint32_t*)&l2;
}

// ---------------------------------------------------------------------------
// fp32 -> bf16 hi/lo splits
// ---------------------------------------------------------------------------
__device__ __forceinline__ void split_body(const float* __restrict__ src,
                                           __nv_bfloat16* __restrict__ hi,
                                           __nv_bfloat16* __restrict__ lo,
                                           int i)
{
    float4 v = *(const float4*)(src + (size_t)i * 4);
    float f[4] = {v.x, v.y, v.z, v.w};
    __nv_bfloat16 h[4], l[4];
#pragma unroll
    for (int j = 0; j < 4; j++) {
        h[j] = __float2bfloat16(f[j]);
        l[j] = __float2bfloat16(f[j] - __bfloat162float(h[j]));
    }
    __nv_bfloat162 hv0 = {h[0], h[1]}, hv1 = {h[2], h[3]};
    __nv_bfloat162 lv0 = {l[0], l[1]}, lv1 = {l[2], l[3]};
    *(__nv_bfloat162*)(hi + (size_t)i * 4)     = hv0;
    *(__nv_bfloat162*)(hi + (size_t)i * 4 + 2) = hv1;
    *(__nv_bfloat162*)(lo + (size_t)i * 4)     = lv0;
    *(__nv_bfloat162*)(lo + (size_t)i * 4 + 2) = lv1;
}

__global__ void __launch_bounds__(256)
split_x_kernel(const float* __restrict__ x, int n4)
{
    int i = blockIdx.x * blockDim.x + threadIdx.x;
    if (i < n4) split_body(x, g_xhi, g_xlo, i);
}

__global__ void __launch_bounds__(256)
split_w_kernel(const float* __restrict__ Wq, const float* __restrict__ Wk,
               const float* __restrict__ Wv, const float* __restrict__ Wo,
               int n4)
{
    int i = blockIdx.x * blockDim.x + threadIdx.x;
    if (i >= n4) return;
    const int z = blockIdx.y;
    const float* src = (z == 0) ? Wq : (z == 1) ? Wk : (z == 2) ? Wv : Wo;
    __nv_bfloat16* hi = (z < 3) ? g_whi + ((size_t)z << 20) : g_wohi;
    __nv_bfloat16* lo = (z < 3) ? g_wlo + ((size_t)z << 20) : g_wolo;
    split_body(src, hi, lo, i);
}

// ---------------------------------------------------------------------------
// mma.sync bf16x3 NT GEMM, KC=64, 2-stage cp.async, ONE barrier per iter.
// CTA tile 128x128, 256 threads = 8 warps, warp tile 32(M) x 64(N).
// Dynamic smem: 2 stages x 4 tiles x [128][72] bf16 = 147456 B.
// ---------------------------------------------------------------------------
#define KC 64
#define LDSG 72
#define GT_BYTES (128 * LDSG * 2)   // 18432 per tile
#define GS_BYTES (4 * GT_BYTES)     // 73728 per stage
#define GEMM_SMEM (2 * GS_BYTES)    // 147456

template <int REMAP>
__device__ __forceinline__ void mma_gemm_body(
    const __nv_bfloat16* __restrict__ Ahi, const __nv_bfloat16* __restrict__ Alo,
    const __nv_bfloat16* __restrict__ Bhi, const __nv_bfloat16* __restrict__ Blo,
    const float* __restrict__ bias, float* __restrict__ out,
    __nv_bfloat16* __restrict__ outhi, __nv_bfloat16* __restrict__ outlo,
    float factor)
{
    extern __shared__ __align__(16) uint8_t dsm[];
    const uint32_t sbase = smem_u32(dsm);

    const int tid  = threadIdx.x;
    const int lane = tid & 31;
    const int wid  = tid >> 5;
    const int wm   = wid & 3;    // M warp group: 32 rows
    const int wn   = wid >> 2;   // N warp group: 64 cols
    const int bm = blockIdx.y * 128;
    const int bn = blockIdx.x * 128;

    float acc[2][8][4];
#pragma unroll
    for (int i = 0; i < 2; i++)
#pragma unroll
        for (int j = 0; j < 8; j++)
#pragma unroll
            for (int c = 0; c < 4; c++) acc[i][j][c] = 0.0f;

    // cp.async: 4 chunks per thread per tile (128 rows x 8 chunks of 16B)
    auto issue = [&](int s, int k0) {
        const uint32_t st = sbase + (uint32_t)s * GS_BYTES;
#pragma unroll
        for (int k = 0; k < 4; k++) {
            const int c   = tid + k * 256;
            const int row = c >> 3;
            const int ce  = (c & 7) * 8;     // element col
            const uint32_t doff = (uint32_t)(row * LDSG + ce) * 2u;
            const size_t aoff = (size_t)(bm + row) * C_DIM + k0 + ce;
            const size_t boff = (size_t)(bn + row) * C_DIM + k0 + ce;
            cp_async16(st + 0 * GT_BYTES + doff, Ahi + aoff);
            cp_async16(st + 1 * GT_BYTES + doff, Alo + aoff);
            cp_async16(st + 2 * GT_BYTES + doff, Bhi + boff);
            cp_async16(st + 3 * GT_BYTES + doff, Blo + boff);
        }
    };

    const int lr = lane & 7;
    const int lm = lane >> 3;          // 0..3
    const int a_row = wm * 32 + (lm & 1) * 8 + lr;
    const int a_col = (lm >> 1) * 8;
    const int b_row = wn * 64 + (lm >> 1) * 8 + lr;
    const int b_col = (lm & 1) * 8;

    const int NK = C_DIM / KC;   // 16
    issue(0, 0); CP_COMMIT();

    for (int kc = 0; kc < NK; kc++) {
        CP_WAIT0();
        __syncthreads();
        if (kc + 1 < NK) { issue((kc + 1) & 1, (kc + 1) * KC); CP_COMMIT(); }

        const uint32_t uAhi = sbase + (uint32_t)(kc & 1) * GS_BYTES;
        const uint32_t uAlo = uAhi + GT_BYTES;
        const uint32_t uBhi = uAhi + 2 * GT_BYTES;
        const uint32_t uBlo = uAhi + 3 * GT_BYTES;

#pragma unroll
        for (int ks = 0; ks < KC / 16; ks++) {
            const int ko = ks * 16;

            uint32_t afh[2][4], afl[2][4];
#pragma unroll
            for (int mi = 0; mi < 2; mi++) {
                const uint32_t off =
                    (uint32_t)((a_row + mi * 16) * LDSG + ko + a_col) * 2u;
                ldmatrix_x4(afh[mi][0], afh[mi][1], afh[mi][2], afh[mi][3], uAhi + off);
                ldmatrix_x4(afl[mi][0], afl[mi][1], afl[mi][2], afl[mi][3], uAlo + off);
            }

            uint32_t bfh[8][2], bfl[8][2];
#pragma unroll
            for (int ni = 0; ni < 4; ni++) {
                const uint32_t off =
                    (uint32_t)((b_row + ni * 16) * LDSG + ko + b_col) * 2u;
                uint32_t r0, r1, r2, r3;
                ldmatrix_x4(r0, r1, r2, r3, uBhi + off);
                bfh[ni * 2][0] = r0; bfh[ni * 2][1] = r1;
                bfh[ni * 2 + 1][0] = r2; bfh[ni * 2 + 1][1] = r3;
                ldmatrix_x4(r0, r1, r2, r3, uBlo + off);
                bfl[ni * 2][0] = r0; bfl[ni * 2][1] = r1;
                bfl[ni * 2 + 1][0] = r2; bfl[ni * 2 + 1][1] = r3;
            }

#pragma unroll
            for (int mi = 0; mi < 2; mi++)
#pragma unroll
                for (int nj = 0; nj < 8; nj++) {
                    mma_16816(acc[mi][nj], afh[mi], bfh[nj]);
                    mma_16816(acc[mi][nj], afh[mi], bfl[nj]);
                    mma_16816(acc[mi][nj], afl[mi], bfh[nj]);
                }
        }
    }

#pragma unroll
    for (int mi = 0; mi < 2; mi++) {
#pragma unroll
        for (int nj = 0; nj < 8; nj++) {
#pragma unroll
            for (int cp = 0; cp < 2; cp++) {
                const int m = bm + wm * 32 + mi * 16 + (lane >> 2) + cp * 8;
                const int n = bn + wn * 64 + nj * 8 + (lane & 3) * 2;
                float v0 = acc[mi][nj][cp * 2 + 0] + bias[n];
                float v1 = acc[mi][nj][cp * 2 + 1] + bias[n + 1];
                if (REMAP == 0) {
                    float2 v; v.x = v0; v.y = v1;
                    *(float2*)&out[(size_t)m * C_DIM + n] = v;
                } else {
                    v0 *= factor; v1 *= factor;
                    uint32_t hw, lw;
                    split_pack(v0, v1, hw, lw);
                    const int b = m >> 11;
                    const int t = m & (T_DIM - 1);
                    const int h = n >> 6;
                    const int d = n & (D_DIM - 1);
                    const size_t idx =
                        (((size_t)(b * H_NUM + h)) * T_DIM + t) * D_DIM + d;
                    *(uint32_t*)&outhi[idx] = hw;
                    *(uint32_t*)&outlo[idx] = lw;
                }
            }
        }
    }
}

__global__ void __launch_bounds__(256, 1)
qkv_mma_kernel(const float* __restrict__ bq, const float* __restrict__ bk,
               const float* __restrict__ bv)
{
    const size_t z = blockIdx.z;
    const __nv_bfloat16* Bh = g_whi + (z << 20);
    const __nv_bfloat16* Bl = g_wlo + (z << 20);
    const float* bias;
    __nv_bfloat16 *oh, *ol;
    float factor;
    if (z == 0)      { bias = bq; oh = g_qhi; ol = g_qlo; factor = Q_FACTOR; }
    else if (z == 1) { bias = bk; oh = g_khi; ol = g_klo; factor = 1.0f; }
    else             { bias = bv; oh = g_vhi; ol = g_vlo; factor = 1.0f; }
    mma_gemm_body<1>(g_xhi, g_xlo, Bh, Bl, bias, nullptr, oh, ol, factor);
}

__global__ void __launch_bounds__(256, 1)
out_mma_kernel(const float* __restrict__ bo, float* __restrict__ out)
{
    mma_gemm_body<0>(g_yhi, g_ylo, g_wohi, g_wolo, bo, out, nullptr, nullptr, 1.0f);
}

// ---------------------------------------------------------------------------
// HMMA flash attention, 512 threads (16 warps = 4/SMSP), q-tile 256 rows.
// Q hi/lo resident in smem (re-ldmatrix'd per k-step to stay <=128 regs).
// 3-stage cp.async K/V pipeline, ONE barrier per iter.
// Warp w owns score rows 16w..16w+15; softmax reductions intra-warp; the
// l (sum) reduction is deferred to the epilogue (lane-partial in the loop).
// Smem: Qhi+Qlo (2 x 256x72) + 3 stages x 4 tiles x (64x72) = 184320 B.
// ---------------------------------------------------------------------------
#define FT_BYTES (64 * 72 * 2)       // 9216 per K/V tile
#define FS_BYTES (4 * FT_BYTES)      // 36864 per stage
#define FQ_BYTES (256 * 72 * 2)      // 36864 per Q tile
#define FLASH_SMEM (2 * FQ_BYTES + 3 * FS_BYTES)  // 184320

__global__ void __launch_bounds__(512, 1)
flash_mma_kernel()
{
    extern __shared__ __align__(16) uint8_t fdsm[];
    const uint32_t sbase  = smem_u32(fdsm);
    const uint32_t uQhi   = sbase;
    const uint32_t uQlo   = sbase + FQ_BYTES;
    const uint32_t stage0 = sbase + 2 * FQ_BYTES;

    const int tid  = threadIdx.x;
    const int lane = tid & 31;
    const int wid  = tid >> 5;           // 0..15
    const int lr = lane & 7;
    const int lm = lane >> 3;
    const int bh = blockIdx.y;
    const int q0 = blockIdx.x * 256;
    const size_t hb = (size_t)bh * T_DIM * D_DIM;

    // ---- load Q hi/lo into resident smem (256 rows x 64 bf16, pitch 72) ----
    {
        const __nv_bfloat16* srch = g_qhi + hb + (size_t)q0 * D_DIM;
        const __nv_bfloat16* srcl = g_qlo + hb + (size_t)q0 * D_DIM;
#pragma unroll
        for (int s = 0; s < 4; s++) {
            const int c   = s * 512 + tid;      // 0..2047
            const int row = c >> 3;
            const int ce  = (c & 7) * 8;
            *(uint4*)(fdsm + row * 144 + ce * 2) =
                *(const uint4*)&srch[row * 64 + ce];
            *(uint4*)(fdsm + FQ_BYTES + row * 144 + ce * 2) =
                *(const uint4*)&srcl[row * 64 + ce];
        }
    }

    // cp.async of one K/V tile-set: 1 chunk per thread per tile
    const int f_row = (tid >> 3) & 63;
    const int f_ce  = (tid & 7) * 8;     // element col
    auto fissue = [&](int s, int k0) {
        const uint32_t st = stage0 + (uint32_t)s * FS_BYTES;
        const uint32_t doff = (uint32_t)(f_row * 72 + f_ce) * 2u;
        const size_t soff = hb + (size_t)(k0 + f_row) * D_DIM + f_ce;
        cp_async16(st + 0 * FT_BYTES + doff, g_khi + soff);
        cp_async16(st + 1 * FT_BYTES + doff, g_klo + soff);
        cp_async16(st + 2 * FT_BYTES + doff, g_vhi + soff);
        cp_async16(st + 3 * FT_BYTES + doff, g_vlo + soff);
    };

    float o[8][4];
#pragma unroll
    for (int j = 0; j < 8; j++)
#pragma unroll
        for (int c = 0; c < 4; c++) o[j][c] = 0.0f;
    float m0 = -1e30f, m1 = -1e30f, l0 = 0.0f, l1 = 0.0f;  // l: lane-partial

    const int arow = wid * 16 + (lm & 1) * 8 + lr;   // Q frag row
    const int acol8 = (lm >> 1) * 8;
    const int brow = (lm >> 1) * 8 + lr;     // K frag row within 16-block
    const int bcol = (lm & 1) * 8;
    const int vcol = (lm >> 1) * 8;          // V frag (trans) col-block
    const int vrow = (lm & 1) * 8 + lr;

    const int NT = T_DIM / 64;   // 32
    fissue(0, 0); CP_COMMIT();
    fissue(1, 64); CP_COMMIT();

    for (int kt = 0; kt < NT; kt++) {
        if (kt + 1 < NT) { CP_WAIT1(); } else { CP_WAIT0(); }
        __syncthreads();   // stage kt visible; also frees slot (kt+2)%3
        if (kt + 2 < NT) { fissue((kt + 2) % 3, (kt + 2) * 64); CP_COMMIT(); }

        const uint32_t uKhi = stage0 + (uint32_t)(kt % 3) * FS_BYTES;
        const uint32_t uKlo = uKhi + FT_BYTES;
        const uint32_t uVhi = uKhi + 2 * FT_BYTES;
        const uint32_t uVlo = uKhi + 3 * FT_BYTES;

        // ---- S = Q * K^T (compensated; Q frags from resident smem) ----
        float sc[8][4];
#pragma unroll
        for (int j = 0; j < 8; j++)
#pragma unroll
            for (int c = 0; c < 4; c++) sc[j][c] = 0.0f;

#pragma unroll
        for (int ks = 0; ks < 4; ks++) {
            const uint32_t qoff = (uint32_t)(arow * 72 + ks * 16 + acol8) * 2u;
            uint32_t qh[4], ql[4];
            ldmatrix_x4(qh[0], qh[1], qh[2], qh[3], uQhi + qoff);
            ldmatrix_x4(ql[0], ql[1], ql[2], ql[3], uQlo + qoff);

            uint32_t bhf[8][2], blf[8][2];
#pragma unroll
            for (int p = 0; p < 4; p++) {
                const uint32_t off =
                    (uint32_t)((p * 16 + brow) * 72 + ks * 16 + bcol) * 2u;
                uint32_t r0, r1, r2, r3;
                ldmatrix_x4(r0, r1, r2, r3, uKhi + off);
                bhf[p * 2][0] = r0; bhf[p * 2][1] = r1;
                bhf[p * 2 + 1][0] = r2; bhf[p * 2 + 1][1] = r3;
                ldmatrix_x4(r0, r1, r2, r3, uKlo + off);
                blf[p * 2][0] = r0; blf[p * 2][1] = r1;
                blf[p * 2 + 1][0] = r2; blf[p * 2 + 1][1] = r3;
            }
#pragma unroll
            for (int j = 0; j < 8; j++) {
                mma_16816(sc[j], qh, bhf[j]);
                mma_16816(sc[j], qh, blf[j]);
                mma_16816(sc[j], ql, bhf[j]);
            }
        }

        // ---- online softmax (log2 domain) ----
        float mx0 = -1e30f, mx1 = -1e30f;
#pragma unroll
        for (int j = 0; j < 8; j++) {
            mx0 = fmaxf(mx0, fmaxf(sc[j][0], sc[j][1]));
            mx1 = fmaxf(mx1, fmaxf(sc[j][2], sc[j][3]));
        }
        mx0 = fmaxf(mx0, __shfl_xor_sync(0xffffffffu, mx0, 1));
        mx0 = fmaxf(mx0, __shfl_xor_sync(0xffffffffu, mx0, 2));
        mx1 = fmaxf(mx1, __shfl_xor_sync(0xffffffffu, mx1, 1));
        mx1 = fmaxf(mx1, __shfl_xor_sync(0xffffffffu, mx1, 2));

        const float M0 = fmaxf(m0, mx0);
        const float M1 = fmaxf(m1, mx1);
        const float c0 = exp2_poly(m0 - M0);
        const float c1 = exp2_poly(m1 - M1);
        m0 = M0; m1 = M1;

        float s0 = 0.0f, s1 = 0.0f;
#pragma unroll
        for (int j = 0; j < 8; j++) {
            sc[j][0] = exp2_poly(sc[j][0] - M0); s0 += sc[j][0];
            sc[j][1] = exp2_poly(sc[j][1] - M0); s0 += sc[j][1];
            sc[j][2] = exp2_poly(sc[j][2] - M1); s1 += sc[j][2];
            sc[j][3] = exp2_poly(sc[j][3] - M1); s1 += sc[j][3];
        }
        l0 = l0 * c0 + s0;      // lane-partial; reduced in epilogue
        l1 = l1 * c1 + s1;
#pragma unroll
        for (int j = 0; j < 8; j++) {
            o[j][0] *= c0; o[j][1] *= c0;
            o[j][2] *= c1; o[j][3] *= c1;
        }

        // ---- O += P * V (P split in regs, V hi/lo; 3-term) ----
#pragma unroll
        for (int ks = 0; ks < 4; ks++) {
            uint32_t ah[4], al[4];
            split_pack(sc[2 * ks][0],     sc[2 * ks][1],     ah[0], al[0]);
            split_pack(sc[2 * ks][2],     sc[2 * ks][3],     ah[1], al[1]);
            split_pack(sc[2 * ks + 1][0], sc[2 * ks + 1][1], ah[2], al[2]);
            split_pack(sc[2 * ks + 1][2], sc[2 * ks + 1][3], ah[3], al[3]);

            uint32_t vh[8][2], vl[8][2];
#pragma unroll
            for (int p = 0; p < 4; p++) {
                const uint32_t off =
                    (uint32_t)((ks * 16 + vrow) * 72 + p * 16 + vcol) * 2u;
                uint32_t r0, r1, r2, r3;
                ldmatrix_x4_trans(r0, r1, r2, r3, uVhi + off);
                vh[p * 2][0] = r0; vh[p * 2][1] = r1;
                vh[p * 2 + 1][0] = r2; vh[p * 2 + 1][1] = r3;
                ldmatrix_x4_trans(r0, r1, r2, r3, uVlo + off);
                vl[p * 2][0] = r0; vl[p * 2][1] = r1;
                vl[p * 2 + 1][0] = r2; vl[p * 2 + 1][1] = r3;
            }
#pragma unroll
            for (int j = 0; j < 8; j++) {
                mma_16816(o[j], ah, vh[j]);
                mma_16816(o[j], ah, vl[j]);
                mma_16816(o[j], al, vh[j]);
            }
        }
    }

    // ---- epilogue: reduce l, normalize, split hi/lo, write y [B,T,C] ----
    l0 += __shfl_xor_sync(0xffffffffu, l0, 1);
    l0 += __shfl_xor_sync(0xffffffffu, l0, 2);
    l1 += __shfl_xor_sync(0xffffffffu, l1, 1);
    l1 += __shfl_xor_sync(0xffffffffu, l1, 2);
    const float inv0 = 1.0f / l0;
    const float inv1 = 1.0f / l1;
    const int b = bh >> 4;
    const int h = bh & 15;
    const int r0row = q0 + wid * 16 + (lane >> 2);
#pragma unroll
    for (int j = 0; j < 8; j++) {
        const int col = h * D_DIM + j * 8 + (lane & 3) * 2;
        uint32_t hw, lw;
        split_pack(o[j][0] * inv0, o[j][1] * inv0, hw, lw);
        size_t idx = ((size_t)b * T_DIM + r0row) * C_DIM + col;
        *(uint32_t*)&g_yhi[idx] = hw;
        *(uint32_t*)&g_ylo[idx] = lw;
        split_pack(o[j][2] * inv1, o[j][3] * inv1, hw, lw);
        idx = ((size_t)b * T_DIM + r0row + 8) * C_DIM + col;
        *(uint32_t*)&g_yhi[idx] = hw;
        *(uint32_t*)&g_ylo[idx] = lw;
    }
}

// ---------------------------------------------------------------------------
extern "C" void kernel_launch(void* const* d_in, const int* in_sizes, int n_in,
                              void* d_out, int out_size)
{
    const float* x  = (const float*)d_in[0];
    const float* Wq = (const float*)d_in[1];
    const float* bq = (const float*)d_in[2];
    const float* Wk = (const float*)d_in[3];
    const float* bk = (const float*)d_in[4];
    const float* Wv = (const float*)d_in[5];
    const float* bv = (const float*)d_in[6];
    const float* Wo = (const float*)d_in[7];
    const float* bo = (const float*)d_in[8];
    float* out = (float*)d_out;

    cudaFuncSetAttribute(qkv_mma_kernel,
                         cudaFuncAttributeMaxDynamicSharedMemorySize, GEMM_SMEM);
    cudaFuncSetAttribute(out_mma_kernel,
                         cudaFuncAttributeMaxDynamicSharedMemorySize, GEMM_SMEM);
    cudaFuncSetAttribute(flash_mma_kernel,
                         cudaFuncAttributeMaxDynamicSharedMemorySize, FLASH_SMEM);

    const int nx4 = M_ROWS * C_DIM / 4;   // 2097152
    const int nw4 = C_DIM * C_DIM / 4;    // 262144

    // 0) fp32 -> bf16 hi/lo splits for X and all weights
    split_x_kernel<<<nx4 / 256, 256>>>(x, nx4);
    {
        dim3 grid(nw4 / 256, 4);
        split_w_kernel<<<grid, 256>>>(Wq, Wk, Wv, Wo, nw4);
    }

    // 1) QKV projections on HMMA -> q/k/v bf16 hi/lo in [B,H,T,D]
    {
        dim3 grid(C_DIM / 128, M_ROWS / 128, 3);
        qkv_mma_kernel<<<grid, 256, GEMM_SMEM>>>(bq, bk, bv);
    }

    // 2) HMMA flash attention -> g_yhi/g_ylo [B,T,C]
    {
        dim3 grid(T_DIM / 256, B_DIM * H_NUM);
        flash_mma_kernel<<<grid, 512, FLASH_SMEM>>>();
    }

    // 3) Output projection on HMMA -> d_out
    {
        dim3 grid(C_DIM / 128, M_ROWS / 128, 1);
        out_mma_kernel<<<grid, 256, GEMM_SMEM>>>(bo, out);
    }
}

// round 17
// speedup vs baseline: 3.6188x; 1.0927x over previous
#include <cuda_runtime.h>
#include <cuda_bf16.h>
#include <cuda_fp16.h>
#include <cstdint>
#include <math.h>

#define B_DIM 4
#define T_DIM 2048
#define C_DIM 1024
#define H_NUM 16
#define D_DIM 64
#define M_ROWS (B_DIM * T_DIM)   // 8192

// Q pre-scale: (1/sqrt(64)) * log2(e)  -> softmax in 2^x domain
#define Q_FACTOR 0.18033688011112042f

// ---------------------------------------------------------------------------
// Scratch (device globals — no allocation allowed).  All 16-bit buffers are
// declared bf16 but are bit-containers; V holds fp16 bits (PV runs fp16 MMA).
// ---------------------------------------------------------------------------
__device__ __nv_bfloat16 g_xhi[(size_t)M_ROWS * C_DIM];
__device__ __nv_bfloat16 g_xlo[(size_t)M_ROWS * C_DIM];
__device__ __nv_bfloat16 g_whi[(size_t)3 * C_DIM * C_DIM];  // Wq,Wk,Wv
__device__ __nv_bfloat16 g_wlo[(size_t)3 * C_DIM * C_DIM];
__device__ __nv_bfloat16 g_wohi[(size_t)C_DIM * C_DIM];
__device__ __nv_bfloat16 g_wolo[(size_t)C_DIM * C_DIM];

__device__ __nv_bfloat16 g_qhi[(size_t)M_ROWS * C_DIM];   // bf16
__device__ __nv_bfloat16 g_qlo[(size_t)M_ROWS * C_DIM];
__device__ __nv_bfloat16 g_khi[(size_t)M_ROWS * C_DIM];   // bf16
__device__ __nv_bfloat16 g_klo[(size_t)M_ROWS * C_DIM];
__device__ __nv_bfloat16 g_vhi[(size_t)M_ROWS * C_DIM];   // fp16 bits!
__device__ __nv_bfloat16 g_vlo[(size_t)M_ROWS * C_DIM];   // fp16 bits!

__device__ __nv_bfloat16 g_yhi[(size_t)M_ROWS * C_DIM];
__device__ __nv_bfloat16 g_ylo[(size_t)M_ROWS * C_DIM];

// ---------------------------------------------------------------------------
// PTX helpers
// ---------------------------------------------------------------------------
__device__ __forceinline__ uint32_t smem_u32(const void* p) {
    uint32_t a;
    asm("{ .reg .u64 t; cvta.to.shared.u64 t, %1; cvt.u32.u64 %0, t; }"
        : "=r"(a) : "l"(p));
    return a;
}

__device__ __forceinline__ void cp_async16(uint32_t dst, const void* src) {
    asm volatile("cp.async.cg.shared.global [%0], [%1], 16;"
                 :: "r"(dst), "l"(src) : "memory");
}
#define CP_COMMIT() asm volatile("cp.async.commit_group;" ::: "memory")
#define CP_WAIT0()  asm volatile("cp.async.wait_group 0;" ::: "memory")
#define CP_WAIT1()  asm volatile("cp.async.wait_group 1;" ::: "memory")

__device__ __forceinline__ void ldmatrix_x4(uint32_t& r0, uint32_t& r1,
                                            uint32_t& r2, uint32_t& r3,
                                            uint32_t addr)
{
    asm volatile("ldmatrix.sync.aligned.m8n8.x4.shared.b16 {%0,%1,%2,%3}, [%4];"
                 : "=r"(r0), "=r"(r1), "=r"(r2), "=r"(r3) : "r"(addr));
}

__device__ __forceinline__ void ldmatrix_x4_trans(uint32_t& r0, uint32_t& r1,
                                                  uint32_t& r2, uint32_t& r3,
                                                  uint32_t addr)
{
    asm volatile("ldmatrix.sync.aligned.m8n8.x4.trans.shared.b16 {%0,%1,%2,%3}, [%4];"
                 : "=r"(r0), "=r"(r1), "=r"(r2), "=r"(r3) : "r"(addr));
}

__device__ __forceinline__ void mma_16816(float* c, const uint32_t* a,
                                          const uint32_t* b)
{
    asm volatile(
        "mma.sync.aligned.m16n8k16.row.col.f32.bf16.bf16.f32 "
        "{%0,%1,%2,%3}, {%4,%5,%6,%7}, {%8,%9}, {%0,%1,%2,%3};"
        : "+f"(c[0]), "+f"(c[1]), "+f"(c[2]), "+f"(c[3])
        : "r"(a[0]), "r"(a[1]), "r"(a[2]), "r"(a[3]), "r"(b[0]), "r"(b[1]));
}

__device__ __forceinline__ void mma_16816h(float* c, const uint32_t* a,
                                           const uint32_t* b)
{
    asm volatile(
        "mma.sync.aligned.m16n8k16.row.col.f32.f16.f16.f32 "
        "{%0,%1,%2,%3}, {%4,%5,%6,%7}, {%8,%9}, {%0,%1,%2,%3};"
        : "+f"(c[0]), "+f"(c[1]), "+f"(c[2]), "+f"(c[3])
        : "r"(a[0]), "r"(a[1]), "r"(a[2]), "r"(a[3]), "r"(b[0]), "r"(b[1]));
}

// exp2 on the FMA pipe: degree-5 poly + exponent splice.  y <= 0 expected.
__device__ __forceinline__ float exp2_poly(float y) {
    y = fmaxf(y, -60.0f);
    float t = __fadd_rn(y, 12582912.0f);          // 1.5 * 2^23: round-to-int
    int   n = __float_as_int(t) - 0x4B400000;     // integer part (can be < 0)
    float f = __fsub_rn(y, __fsub_rn(t, 12582912.0f));   // frac in [-0.5, 0.5]
    float p = 0.0013333558f;
    p = fmaf(p, f, 0.0096181298f);
    p = fmaf(p, f, 0.0555041087f);
    p = fmaf(p, f, 0.2402265069f);
    p = fmaf(p, f, 0.6931471806f);
    p = fmaf(p, f, 1.0f);
    return __int_as_float(__float_as_int(p) + (n << 23));
}

// split (x,y) fp32 pair into packed bf16x2 hi and lo (residual) words
__device__ __forceinline__ void split_pack(float x, float y,
                                           uint32_t& hi, uint32_t& lo)
{
    __nv_bfloat16 hx = __float2bfloat16(x);
    __nv_bfloat16 hy = __float2bfloat16(y);
    float rx = x - __bfloat162float(hx);
    float ry = y - __bfloat162float(hy);
    __nv_bfloat162 h2; h2.x = hx; h2.y = hy;
    __nv_bfloat162 l2; l2.x = __float2bfloat16(rx); l2.y = __float2bfloat16(ry);
    hi = *(uint32_t*)&h2;
    lo = *(uint32_t*)&l2;
}

// split (x,y) fp32 pair into packed fp16x2 hi and lo (residual) words
__device__ __forceinline__ void split_pack_h(float x, float y,
                                             uint32_t& hi, uint32_t& lo)
{
    __half hx = __float2half_rn(x);
    __half hy = __float2half_rn(y);
    float rx = x - __half2float(hx);
    float ry = y - __half2float(hy);
    __half2 h2 = __halves2half2(hx, hy);
    __half2 l2 = __halves2half2(__float2half_rn(rx), __float2half_rn(ry));
    hi = *(uint32_t*)&h2;
    lo = *(uint32_t*)&l2;
}

__device__ __forceinline__ uint32_t pack_h2(float x, float y) {
    __half2 h = __floats2half2_rn(x, y);
    return *(uint32_t*)&h;
}

// ---------------------------------------------------------------------------
// fp32 -> bf16 hi/lo splits
// ---------------------------------------------------------------------------
__device__ __forceinline__ void split_body(const float* __restrict__ src,
                                           __nv_bfloat16* __restrict__ hi,
                                           __nv_bfloat16* __restrict__ lo,
                                           int i)
{
    float4 v = *(const float4*)(src + (size_t)i * 4);
    float f[4] = {v.x, v.y, v.z, v.w};
    __nv_bfloat16 h[4], l[4];
#pragma unroll
    for (int j = 0; j < 4; j++) {
        h[j] = __float2bfloat16(f[j]);
        l[j] = __float2bfloat16(f[j] - __bfloat162float(h[j]));
    }
    __nv_bfloat162 hv0 = {h[0], h[1]}, hv1 = {h[2], h[3]};
    __nv_bfloat162 lv0 = {l[0], l[1]}, lv1 = {l[2], l[3]};
    *(__nv_bfloat162*)(hi + (size_t)i * 4)     = hv0;
    *(__nv_bfloat162*)(hi + (size_t)i * 4 + 2) = hv1;
    *(__nv_bfloat162*)(lo + (size_t)i * 4)     = lv0;
    *(__nv_bfloat162*)(lo + (size_t)i * 4 + 2) = lv1;
}

__global__ void __launch_bounds__(256)
split_x_kernel(const float* __restrict__ x, int n4)
{
    int i = blockIdx.x * blockDim.x + threadIdx.x;
    if (i < n4) split_body(x, g_xhi, g_xlo, i);
}

__global__ void __launch_bounds__(256)
split_w_kernel(const float* __restrict__ Wq, const float* __restrict__ Wk,
               const float* __restrict__ Wv, const float* __restrict__ Wo,
               int n4)
{
    int i = blockIdx.x * blockDim.x + threadIdx.x;
    if (i >= n4) return;
    const int z = blockIdx.y;
    const float* src = (z == 0) ? Wq : (z == 1) ? Wk : (z == 2) ? Wv : Wo;
    __nv_bfloat16* hi = (z < 3) ? g_whi + ((size_t)z << 20) : g_wohi;
    __nv_bfloat16* lo = (z < 3) ? g_wlo + ((size_t)z << 20) : g_wolo;
    split_body(src, hi, lo, i);
}

// ---------------------------------------------------------------------------
// mma.sync bf16x3 NT GEMM, KC=64, 2-stage cp.async, ONE barrier per iter.
// CTA tile 128x128, 256 threads = 8 warps, warp tile 32(M) x 64(N).
// Dynamic smem: 2 stages x 4 tiles x [128][72] bf16 = 147456 B.
// REMAP=1: hi/lo split of res*factor (fp16 when half_out, else bf16).
// ---------------------------------------------------------------------------
#define KC 64
#define LDSG 72
#define GT_BYTES (128 * LDSG * 2)   // 18432 per tile
#define GS_BYTES (4 * GT_BYTES)     // 73728 per stage
#define GEMM_SMEM (2 * GS_BYTES)    // 147456

template <int REMAP>
__device__ __forceinline__ void mma_gemm_body(
    const __nv_bfloat16* __restrict__ Ahi, const __nv_bfloat16* __restrict__ Alo,
    const __nv_bfloat16* __restrict__ Bhi, const __nv_bfloat16* __restrict__ Blo,
    const float* __restrict__ bias, float* __restrict__ out,
    __nv_bfloat16* __restrict__ outhi, __nv_bfloat16* __restrict__ outlo,
    float factor, bool half_out)
{
    extern __shared__ __align__(16) uint8_t dsm[];
    const uint32_t sbase = smem_u32(dsm);

    const int tid  = threadIdx.x;
    const int lane = tid & 31;
    const int wid  = tid >> 5;
    const int wm   = wid & 3;    // M warp group: 32 rows
    const int wn   = wid >> 2;   // N warp group: 64 cols
    const int bm = blockIdx.y * 128;
    const int bn = blockIdx.x * 128;

    float acc[2][8][4];
#pragma unroll
    for (int i = 0; i < 2; i++)
#pragma unroll
        for (int j = 0; j < 8; j++)
#pragma unroll
            for (int c = 0; c < 4; c++) acc[i][j][c] = 0.0f;

    // cp.async: 4 chunks per thread per tile (128 rows x 8 chunks of 16B)
    auto issue = [&](int s, int k0) {
        const uint32_t st = sbase + (uint32_t)s * GS_BYTES;
#pragma unroll
        for (int k = 0; k < 4; k++) {
            const int c   = tid + k * 256;
            const int row = c >> 3;
            const int ce  = (c & 7) * 8;     // element col
            const uint32_t doff = (uint32_t)(row * LDSG + ce) * 2u;
            const size_t aoff = (size_t)(bm + row) * C_DIM + k0 + ce;
            const size_t boff = (size_t)(bn + row) * C_DIM + k0 + ce;
            cp_async16(st + 0 * GT_BYTES + doff, Ahi + aoff);
            cp_async16(st + 1 * GT_BYTES + doff, Alo + aoff);
            cp_async16(st + 2 * GT_BYTES + doff, Bhi + boff);
            cp_async16(st + 3 * GT_BYTES + doff, Blo + boff);
        }
    };

    const int lr = lane & 7;
    const int lm = lane >> 3;          // 0..3
    const int a_row = wm * 32 + (lm & 1) * 8 + lr;
    const int a_col = (lm >> 1) * 8;
    const int b_row = wn * 64 + (lm >> 1) * 8 + lr;
    const int b_col = (lm & 1) * 8;

    const int NK = C_DIM / KC;   // 16
    issue(0, 0); CP_COMMIT();

    for (int kc = 0; kc < NK; kc++) {
        CP_WAIT0();
        __syncthreads();
        if (kc + 1 < NK) { issue((kc + 1) & 1, (kc + 1) * KC); CP_COMMIT(); }

        const uint32_t uAhi = sbase + (uint32_t)(kc & 1) * GS_BYTES;
        const uint32_t uAlo = uAhi + GT_BYTES;
        const uint32_t uBhi = uAhi + 2 * GT_BYTES;
        const uint32_t uBlo = uAhi + 3 * GT_BYTES;

#pragma unroll
        for (int ks = 0; ks < KC / 16; ks++) {
            const int ko = ks * 16;

            uint32_t afh[2][4], afl[2][4];
#pragma unroll
            for (int mi = 0; mi < 2; mi++) {
                const uint32_t off =
                    (uint32_t)((a_row + mi * 16) * LDSG + ko + a_col) * 2u;
                ldmatrix_x4(afh[mi][0], afh[mi][1], afh[mi][2], afh[mi][3], uAhi + off);
                ldmatrix_x4(afl[mi][0], afl[mi][1], afl[mi][2], afl[mi][3], uAlo + off);
            }

            uint32_t bfh[8][2], bfl[8][2];
#pragma unroll
            for (int ni = 0; ni < 4; ni++) {
                const uint32_t off =
                    (uint32_t)((b_row + ni * 16) * LDSG + ko + b_col) * 2u;
                uint32_t r0, r1, r2, r3;
                ldmatrix_x4(r0, r1, r2, r3, uBhi + off);
                bfh[ni * 2][0] = r0; bfh[ni * 2][1] = r1;
                bfh[ni * 2 + 1][0] = r2; bfh[ni * 2 + 1][1] = r3;
                ldmatrix_x4(r0, r1, r2, r3, uBlo + off);
                bfl[ni * 2][0] = r0; bfl[ni * 2][1] = r1;
                bfl[ni * 2 + 1][0] = r2; bfl[ni * 2 + 1][1] = r3;
            }

#pragma unroll
            for (int mi = 0; mi < 2; mi++)
#pragma unroll
                for (int nj = 0; nj < 8; nj++) {
                    mma_16816(acc[mi][nj], afh[mi], bfh[nj]);
                    mma_16816(acc[mi][nj], afh[mi], bfl[nj]);
                    mma_16816(acc[mi][nj], afl[mi], bfh[nj]);
                }
        }
    }

#pragma unroll
    for (int mi = 0; mi < 2; mi++) {
#pragma unroll
        for (int nj = 0; nj < 8; nj++) {
#pragma unroll
            for (int cp = 0; cp < 2; cp++) {
                const int m = bm + wm * 32 + mi * 16 + (lane >> 2) + cp * 8;
                const int n = bn + wn * 64 + nj * 8 + (lane & 3) * 2;
                float v0 = acc[mi][nj][cp * 2 + 0] + bias[n];
                float v1 = acc[mi][nj][cp * 2 + 1] + bias[n + 1];
                if (REMAP == 0) {
                    float2 v; v.x = v0; v.y = v1;
                    *(float2*)&out[(size_t)m * C_DIM + n] = v;
                } else {
                    v0 *= factor; v1 *= factor;
                    uint32_t hw, lw;
                    if (half_out) split_pack_h(v0, v1, hw, lw);
                    else          split_pack(v0, v1, hw, lw);
                    const int b = m >> 11;
                    const int t = m & (T_DIM - 1);
                    const int h = n >> 6;
                    const int d = n & (D_DIM - 1);
                    const size_t idx =
                        (((size_t)(b * H_NUM + h)) * T_DIM + t) * D_DIM + d;
                    *(uint32_t*)&outhi[idx] = hw;
                    *(uint32_t*)&outlo[idx] = lw;
                }
            }
        }
    }
}

__global__ void __launch_bounds__(256, 1)
qkv_mma_kernel(const float* __restrict__ bq, const float* __restrict__ bk,
               const float* __restrict__ bv)
{
    const size_t z = blockIdx.z;
    const __nv_bfloat16* Bh = g_whi + (z << 20);
    const __nv_bfloat16* Bl = g_wlo + (z << 20);
    const float* bias;
    __nv_bfloat16 *oh, *ol;
    float factor;
    bool half_out = false;
    if (z == 0)      { bias = bq; oh = g_qhi; ol = g_qlo; factor = Q_FACTOR; }
    else if (z == 1) { bias = bk; oh = g_khi; ol = g_klo; factor = 1.0f; }
    else             { bias = bv; oh = g_vhi; ol = g_vlo; factor = 1.0f; half_out = true; }
    mma_gemm_body<1>(g_xhi, g_xlo, Bh, Bl, bias, nullptr, oh, ol, factor, half_out);
}

__global__ void __launch_bounds__(256, 1)
out_mma_kernel(const float* __restrict__ bo, float* __restrict__ out)
{
    mma_gemm_body<0>(g_yhi, g_ylo, g_wohi, g_wolo, bo, out, nullptr, nullptr,
                     1.0f, false);
}

// ---------------------------------------------------------------------------
// HMMA flash attention, 512 threads (16 warps), q-tile 256 rows.
// QK: bf16 3-term compensated.  PV: fp16, P single-term + V hi/lo (2 MMAs).
// Q hi/lo resident in smem; 3-stage cp.async K/V pipeline, ONE barrier/iter.
// Smem: Qhi+Qlo (2 x 256x72) + 3 stages x 4 tiles x (64x72) = 184320 B.
// ---------------------------------------------------------------------------
#define FT_BYTES (64 * 72 * 2)       // 9216 per K/V tile
#define FS_BYTES (4 * FT_BYTES)      // 36864 per stage
#define FQ_BYTES (256 * 72 * 2)      // 36864 per Q tile
#define FLASH_SMEM (2 * FQ_BYTES + 3 * FS_BYTES)  // 184320

__global__ void __launch_bounds__(512, 1)
flash_mma_kernel()
{
    extern __shared__ __align__(16) uint8_t fdsm[];
    const uint32_t sbase  = smem_u32(fdsm);
    const uint32_t uQhi   = sbase;
    const uint32_t uQlo   = sbase + FQ_BYTES;
    const uint32_t stage0 = sbase + 2 * FQ_BYTES;

    const int tid  = threadIdx.x;
    const int lane = tid & 31;
    const int wid  = tid >> 5;           // 0..15
    const int lr = lane & 7;
    const int lm = lane >> 3;
    const int bh = blockIdx.y;
    const int q0 = blockIdx.x * 256;
    const size_t hb = (size_t)bh * T_DIM * D_DIM;

    // ---- load Q hi/lo into resident smem (256 rows x 64 bf16, pitch 72) ----
    {
        const __nv_bfloat16* srch = g_qhi + hb + (size_t)q0 * D_DIM;
        const __nv_bfloat16* srcl = g_qlo + hb + (size_t)q0 * D_DIM;
#pragma unroll
        for (int s = 0; s < 4; s++) {
            const int c   = s * 512 + tid;      // 0..2047
            const int row = c >> 3;
            const int ce  = (c & 7) * 8;
            *(uint4*)(fdsm + row * 144 + ce * 2) =
                *(const uint4*)&srch[row * 64 + ce];
            *(uint4*)(fdsm + FQ_BYTES + row * 144 + ce * 2) =
                *(const uint4*)&srcl[row * 64 + ce];
        }
    }

    // cp.async of one K/V tile-set: 1 chunk per thread per tile
    const int f_row = (tid >> 3) & 63;
    const int f_ce  = (tid & 7) * 8;     // element col
    auto fissue = [&](int s, int k0) {
        const uint32_t st = stage0 + (uint32_t)s * FS_BYTES;
        const uint32_t doff = (uint32_t)(f_row * 72 + f_ce) * 2u;
        const size_t soff = hb + (size_t)(k0 + f_row) * D_DIM + f_ce;
        cp_async16(st + 0 * FT_BYTES + doff, g_khi + soff);
        cp_async16(st + 1 * FT_BYTES + doff, g_klo + soff);
        cp_async16(st + 2 * FT_BYTES + doff, g_vhi + soff);
        cp_async16(st + 3 * FT_BYTES + doff, g_vlo + soff);
    };

    float o[8][4];
#pragma unroll
    for (int j = 0; j < 8; j++)
#pragma unroll
        for (int c = 0; c < 4; c++) o[j][c] = 0.0f;
    float m0 = -1e30f, m1 = -1e30f, l0 = 0.0f, l1 = 0.0f;  // l: lane-partial

    const int arow = wid * 16 + (lm & 1) * 8 + lr;   // Q frag row
    const int acol8 = (lm >> 1) * 8;
    const int brow = (lm >> 1) * 8 + lr;     // K frag row within 16-block
    const int bcol = (lm & 1) * 8;
    const int vcol = (lm >> 1) * 8;          // V frag (trans) col-block
    const int vrow = (lm & 1) * 8 + lr;

    const int NT = T_DIM / 64;   // 32
    fissue(0, 0); CP_COMMIT();
    fissue(1, 64); CP_COMMIT();

    for (int kt = 0; kt < NT; kt++) {
        if (kt + 1 < NT) { CP_WAIT1(); } else { CP_WAIT0(); }
        __syncthreads();   // stage kt visible; also frees slot (kt+2)%3
        if (kt + 2 < NT) { fissue((kt + 2) % 3, (kt + 2) * 64); CP_COMMIT(); }

        const uint32_t uKhi = stage0 + (uint32_t)(kt % 3) * FS_BYTES;
        const uint32_t uKlo = uKhi + FT_BYTES;
        const uint32_t uVhi = uKhi + 2 * FT_BYTES;
        const uint32_t uVlo = uKhi + 3 * FT_BYTES;

        // ---- S = Q * K^T (bf16, 3-term compensated) ----
        float sc[8][4];
#pragma unroll
        for (int j = 0; j < 8; j++)
#pragma unroll
            for (int c = 0; c < 4; c++) sc[j][c] = 0.0f;

#pragma unroll
        for (int ks = 0; ks < 4; ks++) {
            const uint32_t qoff = (uint32_t)(arow * 72 + ks * 16 + acol8) * 2u;
            uint32_t qh[4], ql[4];
            ldmatrix_x4(qh[0], qh[1], qh[2], qh[3], uQhi + qoff);
            ldmatrix_x4(ql[0], ql[1], ql[2], ql[3], uQlo + qoff);

            uint32_t bhf[8][2], blf[8][2];
#pragma unroll
            for (int p = 0; p < 4; p++) {
                const uint32_t off =
                    (uint32_t)((p * 16 + brow) * 72 + ks * 16 + bcol) * 2u;
                uint32_t r0, r1, r2, r3;
                ldmatrix_x4(r0, r1, r2, r3, uKhi + off);
                bhf[p * 2][0] = r0; bhf[p * 2][1] = r1;
                bhf[p * 2 + 1][0] = r2; bhf[p * 2 + 1][1] = r3;
                ldmatrix_x4(r0, r1, r2, r3, uKlo + off);
                blf[p * 2][0] = r0; blf[p * 2][1] = r1;
                blf[p * 2 + 1][0] = r2; blf[p * 2 + 1][1] = r3;
            }
#pragma unroll
            for (int j = 0; j < 8; j++) {
                mma_16816(sc[j], qh, bhf[j]);
                mma_16816(sc[j], qh, blf[j]);
                mma_16816(sc[j], ql, bhf[j]);
            }
        }

        // ---- online softmax (log2 domain) ----
        float mx0 = -1e30f, mx1 = -1e30f;
#pragma unroll
        for (int j = 0; j < 8; j++) {
            mx0 = fmaxf(mx0, fmaxf(sc[j][0], sc[j][1]));
            mx1 = fmaxf(mx1, fmaxf(sc[j][2], sc[j][3]));
        }
        mx0 = fmaxf(mx0, __shfl_xor_sync(0xffffffffu, mx0, 1));
        mx0 = fmaxf(mx0, __shfl_xor_sync(0xffffffffu, mx0, 2));
        mx1 = fmaxf(mx1, __shfl_xor_sync(0xffffffffu, mx1, 1));
        mx1 = fmaxf(mx1, __shfl_xor_sync(0xffffffffu, mx1, 2));

        const float M0 = fmaxf(m0, mx0);
        const float M1 = fmaxf(m1, mx1);
        const float c0 = exp2_poly(m0 - M0);
        const float c1 = exp2_poly(m1 - M1);
        m0 = M0; m1 = M1;

        float s0 = 0.0f, s1 = 0.0f;
#pragma unroll
        for (int j = 0; j < 8; j++) {
            sc[j][0] = exp2_poly(sc[j][0] - M0); s0 += sc[j][0];
            sc[j][1] = exp2_poly(sc[j][1] - M0); s0 += sc[j][1];
            sc[j][2] = exp2_poly(sc[j][2] - M1); s1 += sc[j][2];
            sc[j][3] = exp2_poly(sc[j][3] - M1); s1 += sc[j][3];
        }
        l0 = l0 * c0 + s0;      // lane-partial; reduced in epilogue
        l1 = l1 * c1 + s1;
#pragma unroll
        for (int j = 0; j < 8; j++) {
            o[j][0] *= c0; o[j][1] *= c0;
            o[j][2] *= c1; o[j][3] *= c1;
        }

        // ---- O += P * V  (fp16: single-term P, hi/lo V; 2 MMAs per frag) ----
#pragma unroll
        for (int ks = 0; ks < 4; ks++) {
            uint32_t pa[4];
            pa[0] = pack_h2(sc[2 * ks][0],     sc[2 * ks][1]);
            pa[1] = pack_h2(sc[2 * ks][2],     sc[2 * ks][3]);
            pa[2] = pack_h2(sc[2 * ks + 1][0], sc[2 * ks + 1][1]);
            pa[3] = pack_h2(sc[2 * ks + 1][2], sc[2 * ks + 1][3]);

            uint32_t vh[8][2], vl[8][2];
#pragma unroll
            for (int p = 0; p < 4; p++) {
                const uint32_t off =
                    (uint32_t)((ks * 16 + vrow) * 72 + p * 16 + vcol) * 2u;
                uint32_t r0, r1, r2, r3;
                ldmatrix_x4_trans(r0, r1, r2, r3, uVhi + off);
                vh[p * 2][0] = r0; vh[p * 2][1] = r1;
                vh[p * 2 + 1][0] = r2; vh[p * 2 + 1][1] = r3;
                ldmatrix_x4_trans(r0, r1, r2, r3, uVlo + off);
                vl[p * 2][0] = r0; vl[p * 2][1] = r1;
                vl[p * 2 + 1][0] = r2; vl[p * 2 + 1][1] = r3;
            }
#pragma unroll
            for (int j = 0; j < 8; j++) {
                mma_16816h(o[j], pa, vh[j]);
                mma_16816h(o[j], pa, vl[j]);
            }
        }
    }

    // ---- epilogue: reduce l, normalize, split hi/lo, write y [B,T,C] ----
    l0 += __shfl_xor_sync(0xffffffffu, l0, 1);
    l0 += __shfl_xor_sync(0xffffffffu, l0, 2);
    l1 += __shfl_xor_sync(0xffffffffu, l1, 1);
    l1 += __shfl_xor_sync(0xffffffffu, l1, 2);
    const float inv0 = 1.0f / l0;
    const float inv1 = 1.0f / l1;
    const int b = bh >> 4;
    const int h = bh & 15;
    const int r0row = q0 + wid * 16 + (lane >> 2);
#pragma unroll
    for (int j = 0; j < 8; j++) {
        const int col = h * D_DIM + j * 8 + (lane & 3) * 2;
        uint32_t hw, lw;
        split_pack(o[j][0] * inv0, o[j][1] * inv0, hw, lw);
        size_t idx = ((size_t)b * T_DIM + r0row) * C_DIM + col;
        *(uint32_t*)&g_yhi[idx] = hw;
        *(uint32_t*)&g_ylo[idx] = lw;
        split_pack(o[j][2] * inv1, o[j][3] * inv1, hw, lw);
        idx = ((size_t)b * T_DIM + r0row + 8) * C_DIM + col;
        *(uint32_t*)&g_yhi[idx] = hw;
        *(uint32_t*)&g_ylo[idx] = lw;
    }
}

// ---------------------------------------------------------------------------
extern "C" void kernel_launch(void* const* d_in, const int* in_sizes, int n_in,
                              void* d_out, int out_size)
{
    const float* x  = (const float*)d_in[0];
    const float* Wq = (const float*)d_in[1];
    const float* bq = (const float*)d_in[2];
    const float* Wk = (const float*)d_in[3];
    const float* bk = (const float*)d_in[4];
    const float* Wv = (const float*)d_in[5];
    const float* bv = (const float*)d_in[6];
    const float* Wo = (const float*)d_in[7];
    const float* bo = (const float*)d_in[8];
    float* out = (float*)d_out;

    cudaFuncSetAttribute(qkv_mma_kernel,
                         cudaFuncAttributeMaxDynamicSharedMemorySize, GEMM_SMEM);
    cudaFuncSetAttribute(out_mma_kernel,
                         cudaFuncAttributeMaxDynamicSharedMemorySize, GEMM_SMEM);
    cudaFuncSetAttribute(flash_mma_kernel,
                         cudaFuncAttributeMaxDynamicSharedMemorySize, FLASH_SMEM);

    const int nx4 = M_ROWS * C_DIM / 4;   // 2097152
    const int nw4 = C_DIM * C_DIM / 4;    // 262144

    // 0) fp32 -> bf16 hi/lo splits for X and all weights
    split_x_kernel<<<nx4 / 256, 256>>>(x, nx4);
    {
        dim3 grid(nw4 / 256, 4);
        split_w_kernel<<<grid, 256>>>(Wq, Wk, Wv, Wo, nw4);
    }

    // 1) QKV projections on HMMA -> q/k (bf16) and v (fp16) hi/lo in [B,H,T,D]
    {
        dim3 grid(C_DIM / 128, M_ROWS / 128, 3);
        qkv_mma_kernel<<<grid, 256, GEMM_SMEM>>>(bq, bk, bv);
    }

    // 2) HMMA flash attention -> g_yhi/g_ylo [B,T,C]
    {
        dim3 grid(T_DIM / 256, B_DIM * H_NUM);
        flash_mma_kernel<<<grid, 512, FLASH_SMEM>>>();
    }

    // 3) Output projection on HMMA -> d_out
    {
        dim3 grid(C_DIM / 128, M_ROWS / 128, 1);
        out_mma_kernel<<<grid, 256, GEMM_SMEM>>>(bo, out);
    }
}